// round 14
// baseline (speedup 1.0000x reference)
#include <cuda_runtime.h>
#include <cuda_bf16.h>
#include <float.h>

// ---------------------------------------------------------------------------
// DGCNN forward, restructured:
//   EdgeConv(X, W, g, b):  P = X W_a^T ; Q = X (W_b - W_a)^T
//   out[n,c] = bn_lrelu( max_j P[knn(n,j), c] + Q[n,c] )
// kNN via threshold-first filtering (dist matrix never materialized).
// GEMM inner loops: packed fp32 FMA (fma.rn.f32x2), acc packed along rows,
// TBK=16 double-buffered slabs (halved barrier frequency).
// Final GEMM fuses bn+lrelu and the global max/mean pooling partials.
// Top-20 selection + gather + epilogue + next-layer sqnorm fused in one kernel.
// ---------------------------------------------------------------------------

#define BATCH 8
#define NPTS  4096
#define KNN   20
#define NROWS (BATCH * NPTS)   // 32768
#define EPS_BN 1e-5f
#define SLOPE 0.2f
#define NSUB  256
#define CAND_CAP 2048
#define CNT_STRIDE 8           // 32B padding between counters
#define NT 32                  // 4096/128 tiles per side
#define NPAIRS (NT * (NT + 1) / 2)   // 528

// ----------------------------- scratch (device globals) --------------------
__device__ float g_x0[NROWS * 3];
__device__ float g_h[(size_t)NROWS * 512];
__device__ float g_sq[NROWS];
__device__ float g_PQ[(size_t)NROWS * 512];
__device__ float g_wcomb[131072];                 // all layers' [W_a ; W_b-W_a]
__device__ float g_sub[(size_t)NROWS * NSUB];     // subset-dist scratch (32MB)
__device__ float g_thr[NROWS];
__device__ int   g_cnt[NROWS * CNT_STRIDE];
__device__ unsigned long long g_cand[(size_t)NROWS * CAND_CAP];
__device__ float g_pmax[BATCH * 32 * 512];
__device__ float g_psum[BATCH * 32 * 512];

// per-layer offsets into g_wcomb (2C*D each): 384, 8192, 16384, 65536
#define WCO1 0
#define WCO2 (WCO1 + 2 * 64 * 3)
#define WCO3 (WCO2 + 2 * 64 * 64)
#define WCO4 (WCO3 + 2 * 128 * 64)

// ----------------------------- helpers ---------------------------------------

__device__ __forceinline__ unsigned int float_key(float f) {
    unsigned int b = __float_as_uint(f);
    unsigned int mask = (unsigned int)(((int)b) >> 31) | 0x80000000u;
    return b ^ mask;   // monotone: smaller float -> smaller uint
}
// Identical FP sequence in subset GEMM and filter kernel (no reassociation).
__device__ __forceinline__ float dist_val(float sm, float sn, float acc) {
    return __fmaf_rn(-2.0f, acc, __fadd_rn(sm, sn));
}
__device__ __forceinline__ void chain_insert20(unsigned long long loc[KNN],
                                               unsigned long long v) {
#pragma unroll
    for (int t = 0; t < KNN; ++t) {
        if (v < loc[t]) { unsigned long long tmp = loc[t]; loc[t] = v; v = tmp; }
    }
}

// packed f32x2 ops (Blackwell): each lane is an exact rn fp32 FMA
__device__ __forceinline__ unsigned long long pack2(float lo, float hi) {
    unsigned long long d;
    asm("mov.b64 %0, {%1, %2};" : "=l"(d) : "r"(__float_as_uint(lo)), "r"(__float_as_uint(hi)));
    return d;
}
__device__ __forceinline__ void unpack2(unsigned long long v, float& lo, float& hi) {
    unsigned int a, b;
    asm("mov.b64 {%0, %1}, %2;" : "=r"(a), "=r"(b) : "l"(v));
    lo = __uint_as_float(a);
    hi = __uint_as_float(b);
}
__device__ __forceinline__ unsigned long long fma2(unsigned long long a,
                                                   unsigned long long b,
                                                   unsigned long long c) {
    unsigned long long d;
    asm("fma.rn.f32x2 %0, %1, %2, %3;" : "=l"(d) : "l"(a), "l"(b), "l"(c));
    return d;
}

// ----------------------------- small kernels --------------------------------

__global__ void transpose_x_kernel(const float* __restrict__ x, float* __restrict__ xt) {
    int i = blockIdx.x * blockDim.x + threadIdx.x;
    const int total = BATCH * 3 * NPTS;
    if (i >= total) return;
    int b = i / (3 * NPTS);
    int rem = i % (3 * NPTS);
    int d = rem / NPTS;
    int n = rem % NPTS;
    xt[((size_t)b * NPTS + n) * 3 + d] = x[i];
}

__global__ void sqnorm_kernel(const float* __restrict__ X, int lda, int D,
                              float* __restrict__ sq) {
    int i = blockIdx.x * blockDim.x + threadIdx.x;
    if (i >= NROWS) return;
    const float* r = X + (size_t)i * lda;
    float s = 0.f;
    for (int d = 0; d < D; ++d) s += r[d] * r[d];
    sq[i] = s;
}

// Build [W_a ; W_b - W_a] for all four layers in one pass.
__global__ void wcomb_all_kernel(const float* __restrict__ W1,
                                 const float* __restrict__ W2,
                                 const float* __restrict__ W3,
                                 const float* __restrict__ W4,
                                 float* __restrict__ Wc) {
    int i = blockIdx.x * blockDim.x + threadIdx.x;
    const int n1 = 2 * 64 * 3, n2 = 2 * 64 * 64, n3 = 2 * 128 * 64, n4 = 2 * 256 * 128;
    const float* W; int C, D, off, li;
    if (i < n1)                { W = W1; C = 64;  D = 3;   off = WCO1; li = i; }
    else if (i < n1+n2)        { W = W2; C = 64;  D = 64;  off = WCO2; li = i - n1; }
    else if (i < n1+n2+n3)     { W = W3; C = 128; D = 64;  off = WCO3; li = i - n1 - n2; }
    else if (i < n1+n2+n3+n4)  { W = W4; C = 256; D = 128; off = WCO4; li = i - n1 - n2 - n3; }
    else return;
    int c = li / D, d = li % D;
    Wc[off + li] = (c < C) ? W[c * 2 * D + d]
                           : (W[(c - C) * 2 * D + D + d] - W[(c - C) * 2 * D + d]);
}

// ----------------------------- GEMM (store modes) ----------------------------
// NT GEMM:  C[m,n] = sum_k A[m,k] * B[n,k]
// MODE 0: plain store ; MODE 1: dist store ;
// MODE 2: bn+lrelu + fused max/mean pooling partials (no C store)
#define TBM 128
#define TBN 128
#define TBK 16

template <int MODE>
__global__ __launch_bounds__(256, 2)
void gemm_nt_kernel(const float* __restrict__ A, int lda, long long sA,
                    const float* __restrict__ Bw, int ldb, long long sB,
                    float* __restrict__ C, int ldc, long long sC,
                    int M, int Nn, int K,
                    const float* __restrict__ sq, long long sSq,
                    const float* __restrict__ gamma, const float* __restrict__ beta,
                    float* __restrict__ pmax, float* __restrict__ psum) {
    int bz = blockIdx.z;
    A  += (long long)bz * sA;
    Bw += (long long)bz * sB;
    if (MODE != 2) C += (long long)bz * sC;
    const float* sqp = (MODE == 1) ? (sq + (long long)bz * sSq) : nullptr;

    __shared__ __align__(16) float As[2][TBK][TBM + 4];
    __shared__ __align__(16) float Bs[2][TBK][TBN + 4];

    const int m0 = blockIdx.y * TBM;
    const int n0 = blockIdx.x * TBN;
    const int tid = threadIdx.x;
    const int tn = tid % 16;
    const int tm = tid / 16;

    float acc[8][8];

    const bool vec = ((lda % 4) == 0) && ((ldb % 4) == 0) && ((K % TBK) == 0);
    const int lr = tid >> 1;
    const int lp = (tid & 1) * 4;

    if (vec) {
        // accumulators packed along i: acc2[p][j] lanes = (acc[2p][j], acc[2p+1][j])
        unsigned long long acc2[4][8];
#pragma unroll
        for (int p = 0; p < 4; ++p)
#pragma unroll
            for (int j = 0; j < 8; ++j) acc2[p][j] = 0ULL;
        {
            float4 va0 = *(const float4*)(A + (long long)(m0 + lr) * lda + lp);
            float4 va1 = *(const float4*)(A + (long long)(m0 + lr) * lda + lp + 8);
            float4 vb0 = *(const float4*)(Bw + (long long)(n0 + lr) * ldb + lp);
            float4 vb1 = *(const float4*)(Bw + (long long)(n0 + lr) * ldb + lp + 8);
            As[0][lp + 0][lr] = va0.x; As[0][lp + 1][lr] = va0.y;
            As[0][lp + 2][lr] = va0.z; As[0][lp + 3][lr] = va0.w;
            As[0][lp + 8][lr] = va1.x; As[0][lp + 9][lr] = va1.y;
            As[0][lp +10][lr] = va1.z; As[0][lp +11][lr] = va1.w;
            Bs[0][lp + 0][lr] = vb0.x; Bs[0][lp + 1][lr] = vb0.y;
            Bs[0][lp + 2][lr] = vb0.z; Bs[0][lp + 3][lr] = vb0.w;
            Bs[0][lp + 8][lr] = vb1.x; Bs[0][lp + 9][lr] = vb1.y;
            Bs[0][lp +10][lr] = vb1.z; Bs[0][lp +11][lr] = vb1.w;
        }
        __syncthreads();
        int cur = 0;
        for (int k0 = 0; k0 < K; k0 += TBK) {
            const bool has_next = (k0 + TBK) < K;
            float4 na0, na1, nb0, nb1;
            if (has_next) {
                na0 = *(const float4*)(A + (long long)(m0 + lr) * lda + k0 + TBK + lp);
                na1 = *(const float4*)(A + (long long)(m0 + lr) * lda + k0 + TBK + lp + 8);
                nb0 = *(const float4*)(Bw + (long long)(n0 + lr) * ldb + k0 + TBK + lp);
                nb1 = *(const float4*)(Bw + (long long)(n0 + lr) * ldb + k0 + TBK + lp + 8);
            }
#pragma unroll
            for (int kk = 0; kk < TBK; ++kk) {
                const ulonglong2* pa = (const ulonglong2*)&As[cur][kk][tm * 8];
                ulonglong2 a01 = pa[0], a23 = pa[1];
                unsigned long long ap[4] = {a01.x, a01.y, a23.x, a23.y};
                const float4* pb = (const float4*)&Bs[cur][kk][tn * 8];
                float4 b0 = pb[0], b1 = pb[1];
                unsigned long long bj[8];
                bj[0] = pack2(b0.x, b0.x); bj[1] = pack2(b0.y, b0.y);
                bj[2] = pack2(b0.z, b0.z); bj[3] = pack2(b0.w, b0.w);
                bj[4] = pack2(b1.x, b1.x); bj[5] = pack2(b1.y, b1.y);
                bj[6] = pack2(b1.z, b1.z); bj[7] = pack2(b1.w, b1.w);
#pragma unroll
                for (int p = 0; p < 4; ++p)
#pragma unroll
                    for (int j = 0; j < 8; ++j)
                        acc2[p][j] = fma2(ap[p], bj[j], acc2[p][j]);
            }
            if (has_next) {
                int nxt = cur ^ 1;
                As[nxt][lp + 0][lr] = na0.x; As[nxt][lp + 1][lr] = na0.y;
                As[nxt][lp + 2][lr] = na0.z; As[nxt][lp + 3][lr] = na0.w;
                As[nxt][lp + 8][lr] = na1.x; As[nxt][lp + 9][lr] = na1.y;
                As[nxt][lp +10][lr] = na1.z; As[nxt][lp +11][lr] = na1.w;
                Bs[nxt][lp + 0][lr] = nb0.x; Bs[nxt][lp + 1][lr] = nb0.y;
                Bs[nxt][lp + 2][lr] = nb0.z; Bs[nxt][lp + 3][lr] = nb0.w;
                Bs[nxt][lp + 8][lr] = nb1.x; Bs[nxt][lp + 9][lr] = nb1.y;
                Bs[nxt][lp +10][lr] = nb1.z; Bs[nxt][lp +11][lr] = nb1.w;
            }
            __syncthreads();
            cur ^= 1;
        }
#pragma unroll
        for (int p = 0; p < 4; ++p)
#pragma unroll
            for (int j = 0; j < 8; ++j)
                unpack2(acc2[p][j], acc[2 * p][j], acc[2 * p + 1][j]);
    } else {
#pragma unroll
        for (int i = 0; i < 8; ++i)
#pragma unroll
            for (int j = 0; j < 8; ++j) acc[i][j] = 0.f;
        for (int k0 = 0; k0 < K; k0 += TBK) {
            for (int i = tid; i < TBM * TBK; i += 256) {
                int mm = i % TBM, kk = i / TBM;
                int gk = k0 + kk;
                As[0][kk][mm] = (gk < K) ? A[(long long)(m0 + mm) * lda + gk] : 0.f;
            }
            for (int i = tid; i < TBN * TBK; i += 256) {
                int nn = i % TBN, kk = i / TBN;
                int gk = k0 + kk;
                Bs[0][kk][nn] = (gk < K) ? Bw[(long long)(n0 + nn) * ldb + gk] : 0.f;
            }
            __syncthreads();
#pragma unroll
            for (int kk = 0; kk < TBK; ++kk) {
                float ra[8], rb[8];
                const float4* pa = (const float4*)&As[0][kk][tm * 8];
                const float4* pb = (const float4*)&Bs[0][kk][tn * 8];
                float4 a0 = pa[0], a1 = pa[1];
                float4 b0 = pb[0], b1 = pb[1];
                ra[0] = a0.x; ra[1] = a0.y; ra[2] = a0.z; ra[3] = a0.w;
                ra[4] = a1.x; ra[5] = a1.y; ra[6] = a1.z; ra[7] = a1.w;
                rb[0] = b0.x; rb[1] = b0.y; rb[2] = b0.z; rb[3] = b0.w;
                rb[4] = b1.x; rb[5] = b1.y; rb[6] = b1.z; rb[7] = b1.w;
#pragma unroll
                for (int i = 0; i < 8; ++i)
#pragma unroll
                    for (int j = 0; j < 8; ++j) acc[i][j] += ra[i] * rb[j];
            }
            __syncthreads();
        }
    }

    if (MODE == 2) {
        float cmax[8], csum[8];
#pragma unroll
        for (int j = 0; j < 8; ++j) { cmax[j] = -FLT_MAX; csum[j] = 0.f; }
#pragma unroll
        for (int i = 0; i < 8; ++i) {
#pragma unroll
            for (int j = 0; j < 8; ++j) {
                int gn = n0 + tn * 8 + j;
                float s = gamma[gn] * rsqrtf(1.0f + EPS_BN);
                float t = acc[i][j] * s + beta[gn];
                t = (t >= 0.f) ? t : SLOPE * t;
                cmax[j] = fmaxf(cmax[j], t);
                csum[j] += t;
            }
        }
        __syncthreads();
        float2 (*red)[TBN] = (float2 (*)[TBN])&As[0][0][0];   // 16KB
#pragma unroll
        for (int j = 0; j < 8; ++j)
            red[tm][tn * 8 + j] = make_float2(cmax[j], csum[j]);
        __syncthreads();
        if (tid < TBN) {
            float mx = -FLT_MAX, sm = 0.f;
#pragma unroll
            for (int g = 0; g < 16; ++g) {
                float2 r = red[g][tid];
                mx = fmaxf(mx, r.x);
                sm += r.y;
            }
            int b = m0 / NPTS;
            int q = (m0 % NPTS) / TBM;
            int gn = n0 + tid;
            pmax[(b * 32 + q) * 512 + gn] = mx;
            psum[(b * 32 + q) * 512 + gn] = sm;
        }
        return;
    }

#pragma unroll
    for (int i = 0; i < 8; ++i) {
        int gm = m0 + tm * 8 + i;
        float* crow = C + (long long)gm * ldc + n0 + tn * 8;
        float v[8];
        if (MODE == 1) {
            float sm = sqp[gm];
#pragma unroll
            for (int j = 0; j < 8; ++j) {
                int gn = n0 + tn * 8 + j;
                v[j] = dist_val(sm, sqp[gn], acc[i][j]);
            }
        } else {
#pragma unroll
            for (int j = 0; j < 8; ++j) v[j] = acc[i][j];
        }
        ((float4*)crow)[0] = make_float4(v[0], v[1], v[2], v[3]);
        ((float4*)crow)[1] = make_float4(v[4], v[5], v[6], v[7]);
    }
}

// ----------------------- symmetric dist filter (triangular) ------------------
__global__ __launch_bounds__(256, 2)
void dist_filter_kernel(const float* __restrict__ X, int lda, int K,
                        const float* __restrict__ sq,
                        const float* __restrict__ thr,
                        int* __restrict__ cnt,
                        unsigned long long* __restrict__ cand) {
    const int bz = blockIdx.z;
    const float* A = X + (long long)bz * NPTS * lda;
    const float* sqp = sq + (long long)bz * NPTS;
    const float* thrp = thr + (long long)bz * NPTS;
    int* cntp = cnt + (long long)bz * NPTS * CNT_STRIDE;
    unsigned long long* candp = cand + (size_t)bz * NPTS * CAND_CAP;

    int t = blockIdx.x, ty = 0;
    while (t >= NT - ty) { t -= NT - ty; ++ty; }
    const int tx = ty + t;
    const int m0 = ty * TBM;
    const int n0 = tx * TBN;
    const bool offdiag = (tx > ty);

    __shared__ __align__(16) float As[2][TBK][TBM + 4];
    __shared__ __align__(16) float Bs[2][TBK][TBN + 4];

    const int tid = threadIdx.x;
    const int lane = tid & 31;
    const int warp = tid >> 5;
    const int wy = warp >> 1;
    const int wx = warp & 1;
    const int ly = lane >> 3;
    const int lx = lane & 7;
    const int row_off = wy * 32 + ly * 8;
    const int col_off = wx * 64 + lx * 8;

    float acc[8][8];

    const bool vec = ((lda % 4) == 0) && ((K % TBK) == 0);
    const int lr = tid >> 1;
    const int lp = (tid & 1) * 4;

    if (vec) {
        unsigned long long acc2[4][8];
#pragma unroll
        for (int p = 0; p < 4; ++p)
#pragma unroll
            for (int j = 0; j < 8; ++j) acc2[p][j] = 0ULL;
        {
            float4 va0 = *(const float4*)(A + (long long)(m0 + lr) * lda + lp);
            float4 va1 = *(const float4*)(A + (long long)(m0 + lr) * lda + lp + 8);
            float4 vb0 = *(const float4*)(A + (long long)(n0 + lr) * lda + lp);
            float4 vb1 = *(const float4*)(A + (long long)(n0 + lr) * lda + lp + 8);
            As[0][lp + 0][lr] = va0.x; As[0][lp + 1][lr] = va0.y;
            As[0][lp + 2][lr] = va0.z; As[0][lp + 3][lr] = va0.w;
            As[0][lp + 8][lr] = va1.x; As[0][lp + 9][lr] = va1.y;
            As[0][lp +10][lr] = va1.z; As[0][lp +11][lr] = va1.w;
            Bs[0][lp + 0][lr] = vb0.x; Bs[0][lp + 1][lr] = vb0.y;
            Bs[0][lp + 2][lr] = vb0.z; Bs[0][lp + 3][lr] = vb0.w;
            Bs[0][lp + 8][lr] = vb1.x; Bs[0][lp + 9][lr] = vb1.y;
            Bs[0][lp +10][lr] = vb1.z; Bs[0][lp +11][lr] = vb1.w;
        }
        __syncthreads();
        int cur = 0;
        for (int k0 = 0; k0 < K; k0 += TBK) {
            const bool has_next = (k0 + TBK) < K;
            float4 na0, na1, nb0, nb1;
            if (has_next) {
                na0 = *(const float4*)(A + (long long)(m0 + lr) * lda + k0 + TBK + lp);
                na1 = *(const float4*)(A + (long long)(m0 + lr) * lda + k0 + TBK + lp + 8);
                nb0 = *(const float4*)(A + (long long)(n0 + lr) * lda + k0 + TBK + lp);
                nb1 = *(const float4*)(A + (long long)(n0 + lr) * lda + k0 + TBK + lp + 8);
            }
#pragma unroll
            for (int kk = 0; kk < TBK; ++kk) {
                const ulonglong2* pa = (const ulonglong2*)&As[cur][kk][row_off];
                ulonglong2 a01 = pa[0], a23 = pa[1];
                unsigned long long ap[4] = {a01.x, a01.y, a23.x, a23.y};
                const float4* pb = (const float4*)&Bs[cur][kk][col_off];
                float4 b0 = pb[0], b1 = pb[1];
                unsigned long long bj[8];
                bj[0] = pack2(b0.x, b0.x); bj[1] = pack2(b0.y, b0.y);
                bj[2] = pack2(b0.z, b0.z); bj[3] = pack2(b0.w, b0.w);
                bj[4] = pack2(b1.x, b1.x); bj[5] = pack2(b1.y, b1.y);
                bj[6] = pack2(b1.z, b1.z); bj[7] = pack2(b1.w, b1.w);
#pragma unroll
                for (int p = 0; p < 4; ++p)
#pragma unroll
                    for (int j = 0; j < 8; ++j)
                        acc2[p][j] = fma2(ap[p], bj[j], acc2[p][j]);
            }
            if (has_next) {
                int nxt = cur ^ 1;
                As[nxt][lp + 0][lr] = na0.x; As[nxt][lp + 1][lr] = na0.y;
                As[nxt][lp + 2][lr] = na0.z; As[nxt][lp + 3][lr] = na0.w;
                As[nxt][lp + 8][lr] = na1.x; As[nxt][lp + 9][lr] = na1.y;
                As[nxt][lp +10][lr] = na1.z; As[nxt][lp +11][lr] = na1.w;
                Bs[nxt][lp + 0][lr] = nb0.x; Bs[nxt][lp + 1][lr] = nb0.y;
                Bs[nxt][lp + 2][lr] = nb0.z; Bs[nxt][lp + 3][lr] = nb0.w;
                Bs[nxt][lp + 8][lr] = nb1.x; Bs[nxt][lp + 9][lr] = nb1.y;
                Bs[nxt][lp +10][lr] = nb1.z; Bs[nxt][lp +11][lr] = nb1.w;
            }
            __syncthreads();
            cur ^= 1;
        }
#pragma unroll
        for (int p = 0; p < 4; ++p)
#pragma unroll
            for (int j = 0; j < 8; ++j)
                unpack2(acc2[p][j], acc[2 * p][j], acc[2 * p + 1][j]);
    } else {
#pragma unroll
        for (int i = 0; i < 8; ++i)
#pragma unroll
            for (int j = 0; j < 8; ++j) acc[i][j] = 0.f;
        for (int k0 = 0; k0 < K; k0 += TBK) {
            for (int i = tid; i < TBM * TBK; i += 256) {
                int mm = i % TBM, kk = i / TBM;
                int gk = k0 + kk;
                As[0][kk][mm] = (gk < K) ? A[(long long)(m0 + mm) * lda + gk] : 0.f;
            }
            for (int i = tid; i < TBN * TBK; i += 256) {
                int nn = i % TBN, kk = i / TBN;
                int gk = k0 + kk;
                Bs[0][kk][nn] = (gk < K) ? A[(long long)(n0 + nn) * lda + gk] : 0.f;
            }
            __syncthreads();
#pragma unroll
            for (int kk = 0; kk < TBK; ++kk) {
                float ra[8], rb[8];
                const float4* pa = (const float4*)&As[0][kk][row_off];
                const float4* pb = (const float4*)&Bs[0][kk][col_off];
                float4 a0 = pa[0], a1 = pa[1];
                float4 b0 = pb[0], b1 = pb[1];
                ra[0] = a0.x; ra[1] = a0.y; ra[2] = a0.z; ra[3] = a0.w;
                ra[4] = a1.x; ra[5] = a1.y; ra[6] = a1.z; ra[7] = a1.w;
                rb[0] = b0.x; rb[1] = b0.y; rb[2] = b0.z; rb[3] = b0.w;
                rb[4] = b1.x; rb[5] = b1.y; rb[6] = b1.z; rb[7] = b1.w;
#pragma unroll
                for (int i = 0; i < 8; ++i)
#pragma unroll
                    for (int j = 0; j < 8; ++j) acc[i][j] += ra[i] * rb[j];
            }
            __syncthreads();
        }
    }

    float sm[8], sn[8], trr[8], trc[8];
#pragma unroll
    for (int i = 0; i < 8; ++i) {
        sm[i] = sqp[m0 + row_off + i];
        trr[i] = thrp[m0 + row_off + i];
    }
#pragma unroll
    for (int j = 0; j < 8; ++j) {
        sn[j] = sqp[n0 + col_off + j];
        trc[j] = thrp[n0 + col_off + j];
    }
#pragma unroll
    for (int i = 0; i < 8; ++i)
#pragma unroll
        for (int j = 0; j < 8; ++j)
            acc[i][j] = dist_val(sm[i], sn[j], acc[i][j]);

    // ---- row push: 8-lane groups (ly fixed), leader lane = ly*8 ----
    {
        const unsigned grp = 0xFFu << (ly * 8);
        const unsigned below = ((1u << lx) - 1u) << (ly * 8);
        const int leader_lane = ly * 8;
#pragma unroll
        for (int i = 0; i < 8; ++i) {
            const int gm = m0 + row_off + i;
            unsigned pb[8];
            int rank[8];
            int cum = 0;
#pragma unroll
            for (int j = 0; j < 8; ++j) {
                unsigned ball = __ballot_sync(0xFFFFFFFFu, acc[i][j] <= trr[i]) & grp;
                rank[j] = cum + __popc(ball & below);
                cum += __popc(ball);
                pb[j] = ball;
            }
            int base = 0;
            if (lx == 0 && cum > 0) base = atomicAdd(&cntp[gm * CNT_STRIDE], cum);
            base = __shfl_sync(0xFFFFFFFFu, base, leader_lane);
            if (cum > 0) {
                unsigned long long* dst = candp + (size_t)gm * CAND_CAP;
#pragma unroll
                for (int j = 0; j < 8; ++j) {
                    if (pb[j] & (1u << lane)) {
                        int pos = base + rank[j];
                        if (pos < CAND_CAP) {
                            int gn = n0 + col_off + j;
                            dst[pos] = ((unsigned long long)float_key(acc[i][j]) << 32)
                                       | (unsigned int)gn;
                        }
                    }
                }
            }
        }
    }

    // ---- col push (off-diagonal only): 4-lane strided groups (lx fixed) ----
    if (offdiag) {
        const unsigned grp = 0x01010101u << lx;
        const unsigned below = grp & ((1u << lane) - 1u);
        const int leader_lane = lx;
#pragma unroll
        for (int j = 0; j < 8; ++j) {
            const int gn = n0 + col_off + j;
            unsigned pb[8];
            int rank[8];
            int cum = 0;
#pragma unroll
            for (int i = 0; i < 8; ++i) {
                unsigned ball = __ballot_sync(0xFFFFFFFFu, acc[i][j] <= trc[j]) & grp;
                rank[i] = cum + __popc(ball & below);
                cum += __popc(ball);
                pb[i] = ball;
            }
            int base = 0;
            if (ly == 0 && cum > 0) base = atomicAdd(&cntp[gn * CNT_STRIDE], cum);
            base = __shfl_sync(0xFFFFFFFFu, base, leader_lane);
            if (cum > 0) {
                unsigned long long* dst = candp + (size_t)gn * CAND_CAP;
#pragma unroll
                for (int i = 0; i < 8; ++i) {
                    if (pb[i] & (1u << lane)) {
                        int pos = base + rank[i];
                        if (pos < CAND_CAP) {
                            int gm = m0 + row_off + i;
                            dst[pos] = ((unsigned long long)float_key(acc[i][j]) << 32)
                                       | (unsigned int)gm;
                        }
                    }
                }
            }
        }
    }
}

// ----------------------------- threshold from subset -------------------------
__global__ __launch_bounds__(256)
void thr_kernel(const float* __restrict__ sd, float* __restrict__ thr,
                int* __restrict__ cnt) {
    int warp = (blockIdx.x * blockDim.x + threadIdx.x) >> 5;
    int lane = threadIdx.x & 31;
    if (warp >= NROWS) return;
    const float4* row4 = (const float4*)(sd + (size_t)warp * NSUB);

    float loc[KNN];
#pragma unroll
    for (int t = 0; t < KNN; ++t) loc[t] = FLT_MAX;

#pragma unroll
    for (int g = 0; g < 2; ++g) {
        float4 v4 = row4[g * 32 + lane];
        float vals[4] = {v4.x, v4.y, v4.z, v4.w};
#pragma unroll
        for (int s = 0; s < 4; ++s) {
            float v = vals[s];
#pragma unroll
            for (int t = 0; t < KNN; ++t) {
                float mn = fminf(loc[t], v);
                v = fmaxf(loc[t], v);
                loc[t] = mn;
            }
        }
    }

    float thr_f = 0.f;
#pragma unroll
    for (int s = 0; s < KNN; ++s) {
        float v = loc[0];
#pragma unroll
        for (int off = 16; off > 0; off >>= 1)
            v = fminf(v, __shfl_xor_sync(0xFFFFFFFFu, v, off));
        unsigned m = __ballot_sync(0xFFFFFFFFu, loc[0] == v);
        int wlane = __ffs(m) - 1;
        if (lane == wlane) {
#pragma unroll
            for (int t = 0; t < KNN - 1; ++t) loc[t] = loc[t + 1];
            loc[KNN - 1] = FLT_MAX;
        }
        thr_f = v;
    }
    if (lane == 0) {
        thr[warp] = thr_f;
        cnt[warp * CNT_STRIDE] = 0;
    }
}

// -------------- fused: top-20 select + gather + bn/lrelu + sqnorm ------------
__global__ __launch_bounds__(256)
void topk_gather_kernel(const unsigned long long* __restrict__ cand,
                        const int* __restrict__ cnt,
                        const float* __restrict__ PQ,
                        const float* __restrict__ gamma,
                        const float* __restrict__ beta,
                        float* __restrict__ out, int outLd, int C,
                        float* __restrict__ sqout) {
    __shared__ int sidx[8][KNN];
    const int warp = threadIdx.x >> 5;
    const int lane = threadIdx.x & 31;
    const int point = blockIdx.x * 8 + warp;
    const int b = point / NPTS;

    // ---- phase 1: top-20 selection ----
    {
        int c = cnt[point * CNT_STRIDE];
        if (c > CAND_CAP) c = CAND_CAP;
        const unsigned long long* buf = cand + (size_t)point * CAND_CAP;
        const unsigned long long SENT = 0xFFFFFFFFFFFFFFFFULL;
        unsigned long long loc[KNN];
#pragma unroll
        for (int t = 0; t < KNN; ++t) loc[t] = SENT;
        for (int i = lane; i < c; i += 32) chain_insert20(loc, buf[i]);

#pragma unroll
        for (int s = 0; s < KNN; ++s) {
            unsigned long long v = loc[0];
            int wl = lane;
#pragma unroll
            for (int off = 16; off > 0; off >>= 1) {
                unsigned long long ov = __shfl_down_sync(0xFFFFFFFFu, v, off);
                int owl = __shfl_down_sync(0xFFFFFFFFu, wl, off);
                if (ov < v) { v = ov; wl = owl; }
            }
            unsigned long long win = __shfl_sync(0xFFFFFFFFu, v, 0);
            int wlane = __shfl_sync(0xFFFFFFFFu, wl, 0);
            if (lane == 0) sidx[warp][s] = (int)(win & 0xFFFFFFFFu);
            if (lane == wlane) {
#pragma unroll
                for (int t = 0; t < KNN - 1; ++t) loc[t] = loc[t + 1];
                loc[KNN - 1] = SENT;
            }
        }
        __syncwarp();
    }

    // ---- phase 2: gather + epilogue + sqnorm ----
    const int ld = 2 * C;
    const float4* qrow = (const float4*)(PQ + (size_t)point * ld + C);
    float4* orow = (float4*)(out + (size_t)point * outLd);
    const size_t rowbase = (size_t)b * NPTS;
    float ss = 0.f;
    for (int c4 = lane; c4 < C / 4; c4 += 32) {
        float4 m = make_float4(-FLT_MAX, -FLT_MAX, -FLT_MAX, -FLT_MAX);
#pragma unroll 4
        for (int j = 0; j < KNN; ++j) {
            const float4* prow = (const float4*)(PQ + (rowbase + sidx[warp][j]) * ld);
            float4 pv = prow[c4];
            m.x = fmaxf(m.x, pv.x); m.y = fmaxf(m.y, pv.y);
            m.z = fmaxf(m.z, pv.z); m.w = fmaxf(m.w, pv.w);
        }
        float4 q = qrow[c4];
        float4 gg = ((const float4*)gamma)[c4];
        float4 bb = ((const float4*)beta)[c4];
        const float rs = rsqrtf(1.0f + EPS_BN);
        float4 v;
        v.x = (m.x + q.x) * (gg.x * rs) + bb.x;
        v.y = (m.y + q.y) * (gg.y * rs) + bb.y;
        v.z = (m.z + q.z) * (gg.z * rs) + bb.z;
        v.w = (m.w + q.w) * (gg.w * rs) + bb.w;
        v.x = (v.x >= 0.f) ? v.x : SLOPE * v.x;
        v.y = (v.y >= 0.f) ? v.y : SLOPE * v.y;
        v.z = (v.z >= 0.f) ? v.z : SLOPE * v.z;
        v.w = (v.w >= 0.f) ? v.w : SLOPE * v.w;
        orow[c4] = v;
        ss += v.x * v.x + v.y * v.y + v.z * v.z + v.w * v.w;
    }
#pragma unroll
    for (int off = 16; off > 0; off >>= 1)
        ss += __shfl_down_sync(0xFFFFFFFFu, ss, off);
    if (lane == 0) sqout[point] = ss;
}

// ----------------------------- final pool merge -------------------------------
#define PCHUNK 32

__global__ void reduce2_kernel(const float* __restrict__ pmax,
                               const float* __restrict__ psum,
                               float* __restrict__ out) {
    int b = blockIdx.x;
    int c = threadIdx.x;
    float mx = -FLT_MAX, sm = 0.f;
#pragma unroll
    for (int q = 0; q < PCHUNK; ++q) {
        mx = fmaxf(mx, pmax[(b * PCHUNK + q) * 512 + c]);
        sm += psum[(b * PCHUNK + q) * 512 + c];
    }
    out[b * 1024 + c]       = mx;
    out[b * 1024 + 512 + c] = sm * (1.0f / NPTS);
}

// ----------------------------- host driver ----------------------------------

static void run_edge_conv(const float* X, int lda, int D, int C,
                          const float* g, const float* b,
                          float* h_out_col,
                          float* p_sq, float* p_sub, float* p_thr, int* p_cnt,
                          unsigned long long* p_cand,
                          float* p_PQ, const float* p_wc) {
    // subset dist: every point vs first NSUB points of its batch
    dim3 gs(NSUB / TBN, NPTS / TBM, BATCH);
    gemm_nt_kernel<1><<<gs, 256>>>(X, lda, (long long)NPTS * lda,
                                   X, lda, (long long)NPTS * lda,
                                   p_sub, NSUB, (long long)NPTS * NSUB,
                                   NPTS, NSUB, D,
                                   p_sq, NPTS, nullptr, nullptr,
                                   nullptr, nullptr);

    thr_kernel<<<NROWS / 8, 256>>>(p_sub, p_thr, p_cnt);

    // symmetric triangular filter (no dist store)
    dim3 gd(NPAIRS, 1, BATCH);
    dist_filter_kernel<<<gd, 256>>>(X, lda, D, p_sq, p_thr, p_cnt, p_cand);

    dim3 gp((2 * C) / TBN, NROWS / TBM, 1);
    gemm_nt_kernel<0><<<gp, 256>>>(X, lda, 0, p_wc, D, 0,
                                   p_PQ, 2 * C, 0, NROWS, 2 * C, D,
                                   nullptr, 0, nullptr, nullptr,
                                   nullptr, nullptr);

    // fused top-20 + gather + bn/lrelu + sqnorm for the next layer
    topk_gather_kernel<<<NROWS / 8, 256>>>(p_cand, p_cnt, p_PQ, g, b,
                                           h_out_col, 512, C, p_sq);
}

extern "C" void kernel_launch(void* const* d_in, const int* in_sizes, int n_in,
                              void* d_out, int out_size) {
    const float* x = (const float*)d_in[0];
    int wb = 1;
    if (n_in > 1 && in_sizes[1] == 1) wb = 2;

    const float* W1 = (const float*)d_in[wb + 0];
    const float* g1 = (const float*)d_in[wb + 1];
    const float* b1 = (const float*)d_in[wb + 2];
    const float* W2 = (const float*)d_in[wb + 3];
    const float* g2 = (const float*)d_in[wb + 4];
    const float* b2 = (const float*)d_in[wb + 5];
    const float* W3 = (const float*)d_in[wb + 6];
    const float* g3 = (const float*)d_in[wb + 7];
    const float* b3 = (const float*)d_in[wb + 8];
    const float* W4 = (const float*)d_in[wb + 9];
    const float* g4 = (const float*)d_in[wb + 10];
    const float* b4 = (const float*)d_in[wb + 11];
    const float* W5 = (const float*)d_in[wb + 12];
    const float* g5 = (const float*)d_in[wb + 13];
    const float* b5 = (const float*)d_in[wb + 14];

    void *p;
    cudaGetSymbolAddress(&p, g_x0);    float* x0   = (float*)p;
    cudaGetSymbolAddress(&p, g_h);     float* h    = (float*)p;
    cudaGetSymbolAddress(&p, g_sq);    float* sq   = (float*)p;
    cudaGetSymbolAddress(&p, g_PQ);    float* PQ   = (float*)p;
    cudaGetSymbolAddress(&p, g_wcomb); float* wc   = (float*)p;
    cudaGetSymbolAddress(&p, g_sub);   float* sub  = (float*)p;
    cudaGetSymbolAddress(&p, g_thr);   float* thr  = (float*)p;
    cudaGetSymbolAddress(&p, g_cnt);   int*   cnt  = (int*)p;
    cudaGetSymbolAddress(&p, g_cand);  unsigned long long* cand = (unsigned long long*)p;
    cudaGetSymbolAddress(&p, g_pmax);  float* pmax = (float*)p;
    cudaGetSymbolAddress(&p, g_psum);  float* psum = (float*)p;

    transpose_x_kernel<<<(BATCH * 3 * NPTS + 255) / 256, 256>>>(x, x0);
    sqnorm_kernel<<<(NROWS + 255) / 256, 256>>>(x0, 3, 3, sq);
    {
        int total = 2 * (64 * 3 + 64 * 64 + 128 * 64 + 256 * 128);
        wcomb_all_kernel<<<(total + 255) / 256, 256>>>(W1, W2, W3, W4, wc);
    }

    run_edge_conv(x0,      3,   3,   64,  g1, b1, h + 0,   sq, sub, thr, cnt, cand, PQ, wc + WCO1);
    run_edge_conv(h + 0,   512, 64,  64,  g2, b2, h + 64,  sq, sub, thr, cnt, cand, PQ, wc + WCO2);
    run_edge_conv(h + 64,  512, 64,  128, g3, b3, h + 128, sq, sub, thr, cnt, cand, PQ, wc + WCO3);
    run_edge_conv(h + 128, 512, 128, 256, g4, b4, h + 256, sq, sub, thr, cnt, cand, PQ, wc + WCO4);

    // final 1x1 conv (512->512): bn+lrelu + pooling partials fused, no y store
    dim3 gf(512 / TBN, NROWS / TBM, 1);
    gemm_nt_kernel<2><<<gf, 256>>>(h, 512, 0, W5, 512, 0,
                                   nullptr, 0, 0, NROWS, 512, 512,
                                   nullptr, 0, g5, b5,
                                   pmax, psum);

    reduce2_kernel<<<BATCH, 512>>>(pmax, psum, (float*)d_out);
}

// round 15
// speedup vs baseline: 1.0029x; 1.0029x over previous
#include <cuda_runtime.h>
#include <cuda_bf16.h>
#include <float.h>

// ---------------------------------------------------------------------------
// DGCNN forward, restructured:
//   EdgeConv(X, W, g, b):  P = X W_a^T ; Q = X (W_b - W_a)^T
//   out[n,c] = bn_lrelu( max_j P[knn(n,j), c] + Q[n,c] )
// kNN via threshold-first filtering (dist matrix never materialized).
// GEMM inner loops: packed fp32 FMA (fma.rn.f32x2), acc packed along rows,
// TBK=8 double-buffered (measured best occupancy/latency balance).
// Final GEMM fuses bn+lrelu and the global max/mean pooling partials.
// Top-20 selection + gather + epilogue + next-layer sqnorm fused in one kernel.
// ---------------------------------------------------------------------------

#define BATCH 8
#define NPTS  4096
#define KNN   20
#define NROWS (BATCH * NPTS)   // 32768
#define EPS_BN 1e-5f
#define SLOPE 0.2f
#define NSUB  256
#define CAND_CAP 2048
#define CNT_STRIDE 8           // 32B padding between counters
#define NT 32                  // 4096/128 tiles per side
#define NPAIRS (NT * (NT + 1) / 2)   // 528

// ----------------------------- scratch (device globals) --------------------
__device__ float g_x0[NROWS * 3];
__device__ float g_h[(size_t)NROWS * 512];
__device__ float g_sq[NROWS];
__device__ float g_PQ[(size_t)NROWS * 512];
__device__ float g_wcomb[131072];                 // all layers' [W_a ; W_b-W_a]
__device__ float g_sub[(size_t)NROWS * NSUB];     // subset-dist scratch (32MB)
__device__ float g_thr[NROWS];
__device__ int   g_cnt[NROWS * CNT_STRIDE];
__device__ unsigned long long g_cand[(size_t)NROWS * CAND_CAP];
__device__ float g_pmax[BATCH * 32 * 512];
__device__ float g_psum[BATCH * 32 * 512];

// per-layer offsets into g_wcomb (2C*D each)
#define WCO1 0
#define WCO2 (WCO1 + 2 * 64 * 3)
#define WCO3 (WCO2 + 2 * 64 * 64)
#define WCO4 (WCO3 + 2 * 128 * 64)

// ----------------------------- helpers ---------------------------------------

__device__ __forceinline__ unsigned int float_key(float f) {
    unsigned int b = __float_as_uint(f);
    unsigned int mask = (unsigned int)(((int)b) >> 31) | 0x80000000u;
    return b ^ mask;   // monotone: smaller float -> smaller uint
}
// Identical FP sequence in subset GEMM and filter kernel (no reassociation).
__device__ __forceinline__ float dist_val(float sm, float sn, float acc) {
    return __fmaf_rn(-2.0f, acc, __fadd_rn(sm, sn));
}
__device__ __forceinline__ void chain_insert20(unsigned long long loc[KNN],
                                               unsigned long long v) {
#pragma unroll
    for (int t = 0; t < KNN; ++t) {
        if (v < loc[t]) { unsigned long long tmp = loc[t]; loc[t] = v; v = tmp; }
    }
}

// packed f32x2 ops (Blackwell): each lane is an exact rn fp32 FMA
__device__ __forceinline__ unsigned long long pack2(float lo, float hi) {
    unsigned long long d;
    asm("mov.b64 %0, {%1, %2};" : "=l"(d) : "r"(__float_as_uint(lo)), "r"(__float_as_uint(hi)));
    return d;
}
__device__ __forceinline__ void unpack2(unsigned long long v, float& lo, float& hi) {
    unsigned int a, b;
    asm("mov.b64 {%0, %1}, %2;" : "=r"(a), "=r"(b) : "l"(v));
    lo = __uint_as_float(a);
    hi = __uint_as_float(b);
}
__device__ __forceinline__ unsigned long long fma2(unsigned long long a,
                                                   unsigned long long b,
                                                   unsigned long long c) {
    unsigned long long d;
    asm("fma.rn.f32x2 %0, %1, %2, %3;" : "=l"(d) : "l"(a), "l"(b), "l"(c));
    return d;
}

// ----------------------------- small kernels --------------------------------

__global__ void transpose_x_kernel(const float* __restrict__ x, float* __restrict__ xt) {
    int i = blockIdx.x * blockDim.x + threadIdx.x;
    const int total = BATCH * 3 * NPTS;
    if (i >= total) return;
    int b = i / (3 * NPTS);
    int rem = i % (3 * NPTS);
    int d = rem / NPTS;
    int n = rem % NPTS;
    xt[((size_t)b * NPTS + n) * 3 + d] = x[i];
}

__global__ void sqnorm_kernel(const float* __restrict__ X, int lda, int D,
                              float* __restrict__ sq) {
    int i = blockIdx.x * blockDim.x + threadIdx.x;
    if (i >= NROWS) return;
    const float* r = X + (size_t)i * lda;
    float s = 0.f;
    for (int d = 0; d < D; ++d) s += r[d] * r[d];
    sq[i] = s;
}

// Build [W_a ; W_b - W_a] for all four layers in one pass.
__global__ void wcomb_all_kernel(const float* __restrict__ W1,
                                 const float* __restrict__ W2,
                                 const float* __restrict__ W3,
                                 const float* __restrict__ W4,
                                 float* __restrict__ Wc) {
    int i = blockIdx.x * blockDim.x + threadIdx.x;
    const int n1 = 2 * 64 * 3, n2 = 2 * 64 * 64, n3 = 2 * 128 * 64, n4 = 2 * 256 * 128;
    const float* W; int C, D, off, li;
    if (i < n1)                { W = W1; C = 64;  D = 3;   off = WCO1; li = i; }
    else if (i < n1+n2)        { W = W2; C = 64;  D = 64;  off = WCO2; li = i - n1; }
    else if (i < n1+n2+n3)     { W = W3; C = 128; D = 64;  off = WCO3; li = i - n1 - n2; }
    else if (i < n1+n2+n3+n4)  { W = W4; C = 256; D = 128; off = WCO4; li = i - n1 - n2 - n3; }
    else return;
    int c = li / D, d = li % D;
    Wc[off + li] = (c < C) ? W[c * 2 * D + d]
                           : (W[(c - C) * 2 * D + D + d] - W[(c - C) * 2 * D + d]);
}

// ----------------------------- GEMM (store modes) ----------------------------
// NT GEMM:  C[m,n] = sum_k A[m,k] * B[n,k]
// MODE 0: plain store ; MODE 1: dist store ;
// MODE 2: bn+lrelu + fused max/mean pooling partials (no C store)
#define TBM 128
#define TBN 128
#define TBK 8

template <int MODE>
__global__ __launch_bounds__(256, 2)
void gemm_nt_kernel(const float* __restrict__ A, int lda, long long sA,
                    const float* __restrict__ Bw, int ldb, long long sB,
                    float* __restrict__ C, int ldc, long long sC,
                    int M, int Nn, int K,
                    const float* __restrict__ sq, long long sSq,
                    const float* __restrict__ gamma, const float* __restrict__ beta,
                    float* __restrict__ pmax, float* __restrict__ psum) {
    int bz = blockIdx.z;
    A  += (long long)bz * sA;
    Bw += (long long)bz * sB;
    if (MODE != 2) C += (long long)bz * sC;
    const float* sqp = (MODE == 1) ? (sq + (long long)bz * sSq) : nullptr;

    __shared__ __align__(16) float As[2][TBK][TBM + 4];
    __shared__ __align__(16) float Bs[2][TBK][TBN + 4];

    const int m0 = blockIdx.y * TBM;
    const int n0 = blockIdx.x * TBN;
    const int tid = threadIdx.x;
    const int tn = tid % 16;
    const int tm = tid / 16;

    float acc[8][8];

    const bool vec = ((lda % 4) == 0) && ((ldb % 4) == 0) && ((K % TBK) == 0);
    const int lr = tid >> 1;
    const int lp = (tid & 1) * 4;

    if (vec) {
        // accumulators packed along i: acc2[p][j] lanes = (acc[2p][j], acc[2p+1][j])
        unsigned long long acc2[4][8];
#pragma unroll
        for (int p = 0; p < 4; ++p)
#pragma unroll
            for (int j = 0; j < 8; ++j) acc2[p][j] = 0ULL;
        {
            float4 va = *(const float4*)(A + (long long)(m0 + lr) * lda + lp);
            float4 vb = *(const float4*)(Bw + (long long)(n0 + lr) * ldb + lp);
            As[0][lp + 0][lr] = va.x; As[0][lp + 1][lr] = va.y;
            As[0][lp + 2][lr] = va.z; As[0][lp + 3][lr] = va.w;
            Bs[0][lp + 0][lr] = vb.x; Bs[0][lp + 1][lr] = vb.y;
            Bs[0][lp + 2][lr] = vb.z; Bs[0][lp + 3][lr] = vb.w;
        }
        __syncthreads();
        int cur = 0;
        for (int k0 = 0; k0 < K; k0 += TBK) {
            const bool has_next = (k0 + TBK) < K;
            float4 na, nb;
            if (has_next) {
                na = *(const float4*)(A + (long long)(m0 + lr) * lda + k0 + TBK + lp);
                nb = *(const float4*)(Bw + (long long)(n0 + lr) * ldb + k0 + TBK + lp);
            }
#pragma unroll
            for (int kk = 0; kk < TBK; ++kk) {
                const ulonglong2* pa = (const ulonglong2*)&As[cur][kk][tm * 8];
                ulonglong2 a01 = pa[0], a23 = pa[1];
                unsigned long long ap[4] = {a01.x, a01.y, a23.x, a23.y};
                const float4* pb = (const float4*)&Bs[cur][kk][tn * 8];
                float4 b0 = pb[0], b1 = pb[1];
                unsigned long long bj[8];
                bj[0] = pack2(b0.x, b0.x); bj[1] = pack2(b0.y, b0.y);
                bj[2] = pack2(b0.z, b0.z); bj[3] = pack2(b0.w, b0.w);
                bj[4] = pack2(b1.x, b1.x); bj[5] = pack2(b1.y, b1.y);
                bj[6] = pack2(b1.z, b1.z); bj[7] = pack2(b1.w, b1.w);
#pragma unroll
                for (int p = 0; p < 4; ++p)
#pragma unroll
                    for (int j = 0; j < 8; ++j)
                        acc2[p][j] = fma2(ap[p], bj[j], acc2[p][j]);
            }
            if (has_next) {
                int nxt = cur ^ 1;
                As[nxt][lp + 0][lr] = na.x; As[nxt][lp + 1][lr] = na.y;
                As[nxt][lp + 2][lr] = na.z; As[nxt][lp + 3][lr] = na.w;
                Bs[nxt][lp + 0][lr] = nb.x; Bs[nxt][lp + 1][lr] = nb.y;
                Bs[nxt][lp + 2][lr] = nb.z; Bs[nxt][lp + 3][lr] = nb.w;
            }
            __syncthreads();
            cur ^= 1;
        }
#pragma unroll
        for (int p = 0; p < 4; ++p)
#pragma unroll
            for (int j = 0; j < 8; ++j)
                unpack2(acc2[p][j], acc[2 * p][j], acc[2 * p + 1][j]);
    } else {
#pragma unroll
        for (int i = 0; i < 8; ++i)
#pragma unroll
            for (int j = 0; j < 8; ++j) acc[i][j] = 0.f;
        for (int k0 = 0; k0 < K; k0 += TBK) {
            for (int i = tid; i < TBM * TBK; i += 256) {
                int mm = i % TBM, kk = i / TBM;
                int gk = k0 + kk;
                As[0][kk][mm] = (gk < K) ? A[(long long)(m0 + mm) * lda + gk] : 0.f;
            }
            for (int i = tid; i < TBN * TBK; i += 256) {
                int nn = i % TBN, kk = i / TBN;
                int gk = k0 + kk;
                Bs[0][kk][nn] = (gk < K) ? Bw[(long long)(n0 + nn) * ldb + gk] : 0.f;
            }
            __syncthreads();
#pragma unroll
            for (int kk = 0; kk < TBK; ++kk) {
                float ra[8], rb[8];
                const float4* pa = (const float4*)&As[0][kk][tm * 8];
                const float4* pb = (const float4*)&Bs[0][kk][tn * 8];
                float4 a0 = pa[0], a1 = pa[1];
                float4 b0 = pb[0], b1 = pb[1];
                ra[0] = a0.x; ra[1] = a0.y; ra[2] = a0.z; ra[3] = a0.w;
                ra[4] = a1.x; ra[5] = a1.y; ra[6] = a1.z; ra[7] = a1.w;
                rb[0] = b0.x; rb[1] = b0.y; rb[2] = b0.z; rb[3] = b0.w;
                rb[4] = b1.x; rb[5] = b1.y; rb[6] = b1.z; rb[7] = b1.w;
#pragma unroll
                for (int i = 0; i < 8; ++i)
#pragma unroll
                    for (int j = 0; j < 8; ++j) acc[i][j] += ra[i] * rb[j];
            }
            __syncthreads();
        }
    }

    if (MODE == 2) {
        float cmax[8], csum[8];
#pragma unroll
        for (int j = 0; j < 8; ++j) { cmax[j] = -FLT_MAX; csum[j] = 0.f; }
#pragma unroll
        for (int i = 0; i < 8; ++i) {
#pragma unroll
            for (int j = 0; j < 8; ++j) {
                int gn = n0 + tn * 8 + j;
                float s = gamma[gn] * rsqrtf(1.0f + EPS_BN);
                float t = acc[i][j] * s + beta[gn];
                t = (t >= 0.f) ? t : SLOPE * t;
                cmax[j] = fmaxf(cmax[j], t);
                csum[j] += t;
            }
        }
        __syncthreads();
        float2 (*red)[TBN] = (float2 (*)[TBN])&As[0][0][0];   // 16KB
#pragma unroll
        for (int j = 0; j < 8; ++j)
            red[tm][tn * 8 + j] = make_float2(cmax[j], csum[j]);
        __syncthreads();
        if (tid < TBN) {
            float mx = -FLT_MAX, sm = 0.f;
#pragma unroll
            for (int g = 0; g < 16; ++g) {
                float2 r = red[g][tid];
                mx = fmaxf(mx, r.x);
                sm += r.y;
            }
            int b = m0 / NPTS;
            int q = (m0 % NPTS) / TBM;
            int gn = n0 + tid;
            pmax[(b * 32 + q) * 512 + gn] = mx;
            psum[(b * 32 + q) * 512 + gn] = sm;
        }
        return;
    }

#pragma unroll
    for (int i = 0; i < 8; ++i) {
        int gm = m0 + tm * 8 + i;
        float* crow = C + (long long)gm * ldc + n0 + tn * 8;
        float v[8];
        if (MODE == 1) {
            float sm = sqp[gm];
#pragma unroll
            for (int j = 0; j < 8; ++j) {
                int gn = n0 + tn * 8 + j;
                v[j] = dist_val(sm, sqp[gn], acc[i][j]);
            }
        } else {
#pragma unroll
            for (int j = 0; j < 8; ++j) v[j] = acc[i][j];
        }
        ((float4*)crow)[0] = make_float4(v[0], v[1], v[2], v[3]);
        ((float4*)crow)[1] = make_float4(v[4], v[5], v[6], v[7]);
    }
}

// ----------------------- symmetric dist filter (triangular) ------------------
__global__ __launch_bounds__(256, 2)
void dist_filter_kernel(const float* __restrict__ X, int lda, int K,
                        const float* __restrict__ sq,
                        const float* __restrict__ thr,
                        int* __restrict__ cnt,
                        unsigned long long* __restrict__ cand) {
    const int bz = blockIdx.z;
    const float* A = X + (long long)bz * NPTS * lda;
    const float* sqp = sq + (long long)bz * NPTS;
    const float* thrp = thr + (long long)bz * NPTS;
    int* cntp = cnt + (long long)bz * NPTS * CNT_STRIDE;
    unsigned long long* candp = cand + (size_t)bz * NPTS * CAND_CAP;

    int t = blockIdx.x, ty = 0;
    while (t >= NT - ty) { t -= NT - ty; ++ty; }
    const int tx = ty + t;
    const int m0 = ty * TBM;
    const int n0 = tx * TBN;
    const bool offdiag = (tx > ty);

    __shared__ __align__(16) float As[2][TBK][TBM + 4];
    __shared__ __align__(16) float Bs[2][TBK][TBN + 4];

    const int tid = threadIdx.x;
    const int lane = tid & 31;
    const int warp = tid >> 5;
    const int wy = warp >> 1;
    const int wx = warp & 1;
    const int ly = lane >> 3;
    const int lx = lane & 7;
    const int row_off = wy * 32 + ly * 8;
    const int col_off = wx * 64 + lx * 8;

    float acc[8][8];

    const bool vec = ((lda % 4) == 0) && ((K % TBK) == 0);
    const int lr = tid >> 1;
    const int lp = (tid & 1) * 4;

    if (vec) {
        unsigned long long acc2[4][8];
#pragma unroll
        for (int p = 0; p < 4; ++p)
#pragma unroll
            for (int j = 0; j < 8; ++j) acc2[p][j] = 0ULL;
        {
            float4 va = *(const float4*)(A + (long long)(m0 + lr) * lda + lp);
            float4 vb = *(const float4*)(A + (long long)(n0 + lr) * lda + lp);
            As[0][lp + 0][lr] = va.x; As[0][lp + 1][lr] = va.y;
            As[0][lp + 2][lr] = va.z; As[0][lp + 3][lr] = va.w;
            Bs[0][lp + 0][lr] = vb.x; Bs[0][lp + 1][lr] = vb.y;
            Bs[0][lp + 2][lr] = vb.z; Bs[0][lp + 3][lr] = vb.w;
        }
        __syncthreads();
        int cur = 0;
        for (int k0 = 0; k0 < K; k0 += TBK) {
            const bool has_next = (k0 + TBK) < K;
            float4 na, nb;
            if (has_next) {
                na = *(const float4*)(A + (long long)(m0 + lr) * lda + k0 + TBK + lp);
                nb = *(const float4*)(A + (long long)(n0 + lr) * lda + k0 + TBK + lp);
            }
#pragma unroll
            for (int kk = 0; kk < TBK; ++kk) {
                const ulonglong2* pa = (const ulonglong2*)&As[cur][kk][row_off];
                ulonglong2 a01 = pa[0], a23 = pa[1];
                unsigned long long ap[4] = {a01.x, a01.y, a23.x, a23.y};
                const float4* pb = (const float4*)&Bs[cur][kk][col_off];
                float4 b0 = pb[0], b1 = pb[1];
                unsigned long long bj[8];
                bj[0] = pack2(b0.x, b0.x); bj[1] = pack2(b0.y, b0.y);
                bj[2] = pack2(b0.z, b0.z); bj[3] = pack2(b0.w, b0.w);
                bj[4] = pack2(b1.x, b1.x); bj[5] = pack2(b1.y, b1.y);
                bj[6] = pack2(b1.z, b1.z); bj[7] = pack2(b1.w, b1.w);
#pragma unroll
                for (int p = 0; p < 4; ++p)
#pragma unroll
                    for (int j = 0; j < 8; ++j)
                        acc2[p][j] = fma2(ap[p], bj[j], acc2[p][j]);
            }
            if (has_next) {
                int nxt = cur ^ 1;
                As[nxt][lp + 0][lr] = na.x; As[nxt][lp + 1][lr] = na.y;
                As[nxt][lp + 2][lr] = na.z; As[nxt][lp + 3][lr] = na.w;
                Bs[nxt][lp + 0][lr] = nb.x; Bs[nxt][lp + 1][lr] = nb.y;
                Bs[nxt][lp + 2][lr] = nb.z; Bs[nxt][lp + 3][lr] = nb.w;
            }
            __syncthreads();
            cur ^= 1;
        }
#pragma unroll
        for (int p = 0; p < 4; ++p)
#pragma unroll
            for (int j = 0; j < 8; ++j)
                unpack2(acc2[p][j], acc[2 * p][j], acc[2 * p + 1][j]);
    } else {
#pragma unroll
        for (int i = 0; i < 8; ++i)
#pragma unroll
            for (int j = 0; j < 8; ++j) acc[i][j] = 0.f;
        for (int k0 = 0; k0 < K; k0 += TBK) {
            for (int i = tid; i < TBM * TBK; i += 256) {
                int mm = i % TBM, kk = i / TBM;
                int gk = k0 + kk;
                As[0][kk][mm] = (gk < K) ? A[(long long)(m0 + mm) * lda + gk] : 0.f;
            }
            for (int i = tid; i < TBN * TBK; i += 256) {
                int nn = i % TBN, kk = i / TBN;
                int gk = k0 + kk;
                Bs[0][kk][nn] = (gk < K) ? A[(long long)(n0 + nn) * lda + gk] : 0.f;
            }
            __syncthreads();
#pragma unroll
            for (int kk = 0; kk < TBK; ++kk) {
                float ra[8], rb[8];
                const float4* pa = (const float4*)&As[0][kk][row_off];
                const float4* pb = (const float4*)&Bs[0][kk][col_off];
                float4 a0 = pa[0], a1 = pa[1];
                float4 b0 = pb[0], b1 = pb[1];
                ra[0] = a0.x; ra[1] = a0.y; ra[2] = a0.z; ra[3] = a0.w;
                ra[4] = a1.x; ra[5] = a1.y; ra[6] = a1.z; ra[7] = a1.w;
                rb[0] = b0.x; rb[1] = b0.y; rb[2] = b0.z; rb[3] = b0.w;
                rb[4] = b1.x; rb[5] = b1.y; rb[6] = b1.z; rb[7] = b1.w;
#pragma unroll
                for (int i = 0; i < 8; ++i)
#pragma unroll
                    for (int j = 0; j < 8; ++j) acc[i][j] += ra[i] * rb[j];
            }
            __syncthreads();
        }
    }

    float sm[8], sn[8], trr[8], trc[8];
#pragma unroll
    for (int i = 0; i < 8; ++i) {
        sm[i] = sqp[m0 + row_off + i];
        trr[i] = thrp[m0 + row_off + i];
    }
#pragma unroll
    for (int j = 0; j < 8; ++j) {
        sn[j] = sqp[n0 + col_off + j];
        trc[j] = thrp[n0 + col_off + j];
    }
#pragma unroll
    for (int i = 0; i < 8; ++i)
#pragma unroll
        for (int j = 0; j < 8; ++j)
            acc[i][j] = dist_val(sm[i], sn[j], acc[i][j]);

    // ---- row push: 8-lane groups (ly fixed), leader lane = ly*8 ----
    {
        const unsigned grp = 0xFFu << (ly * 8);
        const unsigned below = ((1u << lx) - 1u) << (ly * 8);
        const int leader_lane = ly * 8;
#pragma unroll
        for (int i = 0; i < 8; ++i) {
            const int gm = m0 + row_off + i;
            unsigned pb[8];
            int rank[8];
            int cum = 0;
#pragma unroll
            for (int j = 0; j < 8; ++j) {
                unsigned ball = __ballot_sync(0xFFFFFFFFu, acc[i][j] <= trr[i]) & grp;
                rank[j] = cum + __popc(ball & below);
                cum += __popc(ball);
                pb[j] = ball;
            }
            int base = 0;
            if (lx == 0 && cum > 0) base = atomicAdd(&cntp[gm * CNT_STRIDE], cum);
            base = __shfl_sync(0xFFFFFFFFu, base, leader_lane);
            if (cum > 0) {
                unsigned long long* dst = candp + (size_t)gm * CAND_CAP;
#pragma unroll
                for (int j = 0; j < 8; ++j) {
                    if (pb[j] & (1u << lane)) {
                        int pos = base + rank[j];
                        if (pos < CAND_CAP) {
                            int gn = n0 + col_off + j;
                            dst[pos] = ((unsigned long long)float_key(acc[i][j]) << 32)
                                       | (unsigned int)gn;
                        }
                    }
                }
            }
        }
    }

    // ---- col push (off-diagonal only): 4-lane strided groups (lx fixed) ----
    if (offdiag) {
        const unsigned grp = 0x01010101u << lx;
        const unsigned below = grp & ((1u << lane) - 1u);
        const int leader_lane = lx;
#pragma unroll
        for (int j = 0; j < 8; ++j) {
            const int gn = n0 + col_off + j;
            unsigned pb[8];
            int rank[8];
            int cum = 0;
#pragma unroll
            for (int i = 0; i < 8; ++i) {
                unsigned ball = __ballot_sync(0xFFFFFFFFu, acc[i][j] <= trc[j]) & grp;
                rank[i] = cum + __popc(ball & below);
                cum += __popc(ball);
                pb[i] = ball;
            }
            int base = 0;
            if (ly == 0 && cum > 0) base = atomicAdd(&cntp[gn * CNT_STRIDE], cum);
            base = __shfl_sync(0xFFFFFFFFu, base, leader_lane);
            if (cum > 0) {
                unsigned long long* dst = candp + (size_t)gn * CAND_CAP;
#pragma unroll
                for (int i = 0; i < 8; ++i) {
                    if (pb[i] & (1u << lane)) {
                        int pos = base + rank[i];
                        if (pos < CAND_CAP) {
                            int gm = m0 + row_off + i;
                            dst[pos] = ((unsigned long long)float_key(acc[i][j]) << 32)
                                       | (unsigned int)gm;
                        }
                    }
                }
            }
        }
    }
}

// ----------------------------- threshold from subset -------------------------
__global__ __launch_bounds__(256)
void thr_kernel(const float* __restrict__ sd, float* __restrict__ thr,
                int* __restrict__ cnt) {
    int warp = (blockIdx.x * blockDim.x + threadIdx.x) >> 5;
    int lane = threadIdx.x & 31;
    if (warp >= NROWS) return;
    const float4* row4 = (const float4*)(sd + (size_t)warp * NSUB);

    float loc[KNN];
#pragma unroll
    for (int t = 0; t < KNN; ++t) loc[t] = FLT_MAX;

#pragma unroll
    for (int g = 0; g < 2; ++g) {
        float4 v4 = row4[g * 32 + lane];
        float vals[4] = {v4.x, v4.y, v4.z, v4.w};
#pragma unroll
        for (int s = 0; s < 4; ++s) {
            float v = vals[s];
#pragma unroll
            for (int t = 0; t < KNN; ++t) {
                float mn = fminf(loc[t], v);
                v = fmaxf(loc[t], v);
                loc[t] = mn;
            }
        }
    }

    float thr_f = 0.f;
#pragma unroll
    for (int s = 0; s < KNN; ++s) {
        float v = loc[0];
#pragma unroll
        for (int off = 16; off > 0; off >>= 1)
            v = fminf(v, __shfl_xor_sync(0xFFFFFFFFu, v, off));
        unsigned m = __ballot_sync(0xFFFFFFFFu, loc[0] == v);
        int wlane = __ffs(m) - 1;
        if (lane == wlane) {
#pragma unroll
            for (int t = 0; t < KNN - 1; ++t) loc[t] = loc[t + 1];
            loc[KNN - 1] = FLT_MAX;
        }
        thr_f = v;
    }
    if (lane == 0) {
        thr[warp] = thr_f;
        cnt[warp * CNT_STRIDE] = 0;
    }
}

// -------------- fused: top-20 select + gather + bn/lrelu + sqnorm ------------
__global__ __launch_bounds__(256)
void topk_gather_kernel(const unsigned long long* __restrict__ cand,
                        const int* __restrict__ cnt,
                        const float* __restrict__ PQ,
                        const float* __restrict__ gamma,
                        const float* __restrict__ beta,
                        float* __restrict__ out, int outLd, int C,
                        float* __restrict__ sqout) {
    __shared__ int sidx[8][KNN];
    const int warp = threadIdx.x >> 5;
    const int lane = threadIdx.x & 31;
    const int point = blockIdx.x * 8 + warp;
    const int b = point / NPTS;

    // ---- phase 1: top-20 selection ----
    {
        int c = cnt[point * CNT_STRIDE];
        if (c > CAND_CAP) c = CAND_CAP;
        const unsigned long long* buf = cand + (size_t)point * CAND_CAP;
        const unsigned long long SENT = 0xFFFFFFFFFFFFFFFFULL;
        unsigned long long loc[KNN];
#pragma unroll
        for (int t = 0; t < KNN; ++t) loc[t] = SENT;
        for (int i = lane; i < c; i += 32) chain_insert20(loc, buf[i]);

#pragma unroll
        for (int s = 0; s < KNN; ++s) {
            unsigned long long v = loc[0];
            int wl = lane;
#pragma unroll
            for (int off = 16; off > 0; off >>= 1) {
                unsigned long long ov = __shfl_down_sync(0xFFFFFFFFu, v, off);
                int owl = __shfl_down_sync(0xFFFFFFFFu, wl, off);
                if (ov < v) { v = ov; wl = owl; }
            }
            unsigned long long win = __shfl_sync(0xFFFFFFFFu, v, 0);
            int wlane = __shfl_sync(0xFFFFFFFFu, wl, 0);
            if (lane == 0) sidx[warp][s] = (int)(win & 0xFFFFFFFFu);
            if (lane == wlane) {
#pragma unroll
                for (int t = 0; t < KNN - 1; ++t) loc[t] = loc[t + 1];
                loc[KNN - 1] = SENT;
            }
        }
        __syncwarp();
    }

    // ---- phase 2: gather + epilogue + sqnorm ----
    const int ld = 2 * C;
    const float4* qrow = (const float4*)(PQ + (size_t)point * ld + C);
    float4* orow = (float4*)(out + (size_t)point * outLd);
    const size_t rowbase = (size_t)b * NPTS;
    float ss = 0.f;
    for (int c4 = lane; c4 < C / 4; c4 += 32) {
        float4 m = make_float4(-FLT_MAX, -FLT_MAX, -FLT_MAX, -FLT_MAX);
#pragma unroll 4
        for (int j = 0; j < KNN; ++j) {
            const float4* prow = (const float4*)(PQ + (rowbase + sidx[warp][j]) * ld);
            float4 pv = prow[c4];
            m.x = fmaxf(m.x, pv.x); m.y = fmaxf(m.y, pv.y);
            m.z = fmaxf(m.z, pv.z); m.w = fmaxf(m.w, pv.w);
        }
        float4 q = qrow[c4];
        float4 gg = ((const float4*)gamma)[c4];
        float4 bb = ((const float4*)beta)[c4];
        const float rs = rsqrtf(1.0f + EPS_BN);
        float4 v;
        v.x = (m.x + q.x) * (gg.x * rs) + bb.x;
        v.y = (m.y + q.y) * (gg.y * rs) + bb.y;
        v.z = (m.z + q.z) * (gg.z * rs) + bb.z;
        v.w = (m.w + q.w) * (gg.w * rs) + bb.w;
        v.x = (v.x >= 0.f) ? v.x : SLOPE * v.x;
        v.y = (v.y >= 0.f) ? v.y : SLOPE * v.y;
        v.z = (v.z >= 0.f) ? v.z : SLOPE * v.z;
        v.w = (v.w >= 0.f) ? v.w : SLOPE * v.w;
        orow[c4] = v;
        ss += v.x * v.x + v.y * v.y + v.z * v.z + v.w * v.w;
    }
#pragma unroll
    for (int off = 16; off > 0; off >>= 1)
        ss += __shfl_down_sync(0xFFFFFFFFu, ss, off);
    if (lane == 0) sqout[point] = ss;
}

// ----------------------------- final pool merge -------------------------------
#define PCHUNK 32

__global__ void reduce2_kernel(const float* __restrict__ pmax,
                               const float* __restrict__ psum,
                               float* __restrict__ out) {
    int b = blockIdx.x;
    int c = threadIdx.x;
    float mx = -FLT_MAX, sm = 0.f;
#pragma unroll
    for (int q = 0; q < PCHUNK; ++q) {
        mx = fmaxf(mx, pmax[(b * PCHUNK + q) * 512 + c]);
        sm += psum[(b * PCHUNK + q) * 512 + c];
    }
    out[b * 1024 + c]       = mx;
    out[b * 1024 + 512 + c] = sm * (1.0f / NPTS);
}

// ----------------------------- host driver ----------------------------------

static void run_edge_conv(const float* X, int lda, int D, int C,
                          const float* g, const float* b,
                          float* h_out_col,
                          float* p_sq, float* p_sub, float* p_thr, int* p_cnt,
                          unsigned long long* p_cand,
                          float* p_PQ, const float* p_wc) {
    // subset dist: every point vs first NSUB points of its batch
    dim3 gs(NSUB / TBN, NPTS / TBM, BATCH);
    gemm_nt_kernel<1><<<gs, 256>>>(X, lda, (long long)NPTS * lda,
                                   X, lda, (long long)NPTS * lda,
                                   p_sub, NSUB, (long long)NPTS * NSUB,
                                   NPTS, NSUB, D,
                                   p_sq, NPTS, nullptr, nullptr,
                                   nullptr, nullptr);

    thr_kernel<<<NROWS / 8, 256>>>(p_sub, p_thr, p_cnt);

    // symmetric triangular filter (no dist store)
    dim3 gd(NPAIRS, 1, BATCH);
    dist_filter_kernel<<<gd, 256>>>(X, lda, D, p_sq, p_thr, p_cnt, p_cand);

    dim3 gp((2 * C) / TBN, NROWS / TBM, 1);
    gemm_nt_kernel<0><<<gp, 256>>>(X, lda, 0, p_wc, D, 0,
                                   p_PQ, 2 * C, 0, NROWS, 2 * C, D,
                                   nullptr, 0, nullptr, nullptr,
                                   nullptr, nullptr);

    // fused top-20 + gather + bn/lrelu + sqnorm for the next layer
    topk_gather_kernel<<<NROWS / 8, 256>>>(p_cand, p_cnt, p_PQ, g, b,
                                           h_out_col, 512, C, p_sq);
}

extern "C" void kernel_launch(void* const* d_in, const int* in_sizes, int n_in,
                              void* d_out, int out_size) {
    const float* x = (const float*)d_in[0];
    int wb = 1;
    if (n_in > 1 && in_sizes[1] == 1) wb = 2;

    const float* W1 = (const float*)d_in[wb + 0];
    const float* g1 = (const float*)d_in[wb + 1];
    const float* b1 = (const float*)d_in[wb + 2];
    const float* W2 = (const float*)d_in[wb + 3];
    const float* g2 = (const float*)d_in[wb + 4];
    const float* b2 = (const float*)d_in[wb + 5];
    const float* W3 = (const float*)d_in[wb + 6];
    const float* g3 = (const float*)d_in[wb + 7];
    const float* b3 = (const float*)d_in[wb + 8];
    const float* W4 = (const float*)d_in[wb + 9];
    const float* g4 = (const float*)d_in[wb + 10];
    const float* b4 = (const float*)d_in[wb + 11];
    const float* W5 = (const float*)d_in[wb + 12];
    const float* g5 = (const float*)d_in[wb + 13];
    const float* b5 = (const float*)d_in[wb + 14];

    void *p;
    cudaGetSymbolAddress(&p, g_x0);    float* x0   = (float*)p;
    cudaGetSymbolAddress(&p, g_h);     float* h    = (float*)p;
    cudaGetSymbolAddress(&p, g_sq);    float* sq   = (float*)p;
    cudaGetSymbolAddress(&p, g_PQ);    float* PQ   = (float*)p;
    cudaGetSymbolAddress(&p, g_wcomb); float* wc   = (float*)p;
    cudaGetSymbolAddress(&p, g_sub);   float* sub  = (float*)p;
    cudaGetSymbolAddress(&p, g_thr);   float* thr  = (float*)p;
    cudaGetSymbolAddress(&p, g_cnt);   int*   cnt  = (int*)p;
    cudaGetSymbolAddress(&p, g_cand);  unsigned long long* cand = (unsigned long long*)p;
    cudaGetSymbolAddress(&p, g_pmax);  float* pmax = (float*)p;
    cudaGetSymbolAddress(&p, g_psum);  float* psum = (float*)p;

    transpose_x_kernel<<<(BATCH * 3 * NPTS + 255) / 256, 256>>>(x, x0);
    sqnorm_kernel<<<(NROWS + 255) / 256, 256>>>(x0, 3, 3, sq);
    {
        int total = 2 * (64 * 3 + 64 * 64 + 128 * 64 + 256 * 128);
        wcomb_all_kernel<<<(total + 255) / 256, 256>>>(W1, W2, W3, W4, wc);
    }

    run_edge_conv(x0,      3,   3,   64,  g1, b1, h + 0,   sq, sub, thr, cnt, cand, PQ, wc + WCO1);
    run_edge_conv(h + 0,   512, 64,  64,  g2, b2, h + 64,  sq, sub, thr, cnt, cand, PQ, wc + WCO2);
    run_edge_conv(h + 64,  512, 64,  128, g3, b3, h + 128, sq, sub, thr, cnt, cand, PQ, wc + WCO3);
    run_edge_conv(h + 128, 512, 128, 256, g4, b4, h + 256, sq, sub, thr, cnt, cand, PQ, wc + WCO4);

    // final 1x1 conv (512->512): bn+lrelu + pooling partials fused, no y store
    dim3 gf(512 / TBN, NROWS / TBM, 1);
    gemm_nt_kernel<2><<<gf, 256>>>(h, 512, 0, W5, 512, 0,
                                   nullptr, 0, 0, NROWS, 512, 512,
                                   nullptr, 0, g5, b5,
                                   pmax, psum);

    reduce2_kernel<<<BATCH, 512>>>(pmax, psum, (float*)d_out);
}

// round 16
// speedup vs baseline: 1.0088x; 1.0059x over previous
#include <cuda_runtime.h>
#include <cuda_bf16.h>
#include <float.h>

// ---------------------------------------------------------------------------
// DGCNN forward, restructured:
//   EdgeConv(X, W, g, b):  P = X W_a^T ; Q = X (W_b - W_a)^T
//   out[n,c] = bn_lrelu( max_j P[knn(n,j), c] + Q[n,c] )
// kNN via threshold-first filtering (dist matrix never materialized).
// GEMM inner loops: packed fp32 FMA (fma.rn.f32x2), acc packed along rows,
// TBK=8 double-buffered (measured best occupancy/latency balance).
// Final GEMM fuses bn+lrelu and the global max/mean pooling partials.
// Top-20 selection + gather + epilogue + next-layer sqnorm fused in one kernel;
// C=64 layers split the neighbor loop across lane pairs (no idle half-warp).
// ---------------------------------------------------------------------------

#define BATCH 8
#define NPTS  4096
#define KNN   20
#define NROWS (BATCH * NPTS)   // 32768
#define EPS_BN 1e-5f
#define SLOPE 0.2f
#define NSUB  256
#define CAND_CAP 2048
#define CNT_STRIDE 8           // 32B padding between counters
#define NT 32                  // 4096/128 tiles per side
#define NPAIRS (NT * (NT + 1) / 2)   // 528

// ----------------------------- scratch (device globals) --------------------
__device__ float g_x0[NROWS * 3];
__device__ float g_h[(size_t)NROWS * 512];
__device__ float g_sq[NROWS];
__device__ float g_PQ[(size_t)NROWS * 512];
__device__ float g_wcomb[131072];                 // all layers' [W_a ; W_b-W_a]
__device__ float g_sub[(size_t)NROWS * NSUB];     // subset-dist scratch (32MB)
__device__ float g_thr[NROWS];
__device__ int   g_cnt[NROWS * CNT_STRIDE];
__device__ unsigned long long g_cand[(size_t)NROWS * CAND_CAP];
__device__ float g_pmax[BATCH * 32 * 512];
__device__ float g_psum[BATCH * 32 * 512];

// per-layer offsets into g_wcomb (2C*D each)
#define WCO1 0
#define WCO2 (WCO1 + 2 * 64 * 3)
#define WCO3 (WCO2 + 2 * 64 * 64)
#define WCO4 (WCO3 + 2 * 128 * 64)

// ----------------------------- helpers ---------------------------------------

__device__ __forceinline__ unsigned int float_key(float f) {
    unsigned int b = __float_as_uint(f);
    unsigned int mask = (unsigned int)(((int)b) >> 31) | 0x80000000u;
    return b ^ mask;   // monotone: smaller float -> smaller uint
}
// Identical FP sequence in subset GEMM and filter kernel (no reassociation).
__device__ __forceinline__ float dist_val(float sm, float sn, float acc) {
    return __fmaf_rn(-2.0f, acc, __fadd_rn(sm, sn));
}
__device__ __forceinline__ void chain_insert20(unsigned long long loc[KNN],
                                               unsigned long long v) {
#pragma unroll
    for (int t = 0; t < KNN; ++t) {
        if (v < loc[t]) { unsigned long long tmp = loc[t]; loc[t] = v; v = tmp; }
    }
}

// packed f32x2 ops (Blackwell): each lane is an exact rn fp32 FMA
__device__ __forceinline__ unsigned long long pack2(float lo, float hi) {
    unsigned long long d;
    asm("mov.b64 %0, {%1, %2};" : "=l"(d) : "r"(__float_as_uint(lo)), "r"(__float_as_uint(hi)));
    return d;
}
__device__ __forceinline__ void unpack2(unsigned long long v, float& lo, float& hi) {
    unsigned int a, b;
    asm("mov.b64 {%0, %1}, %2;" : "=r"(a), "=r"(b) : "l"(v));
    lo = __uint_as_float(a);
    hi = __uint_as_float(b);
}
__device__ __forceinline__ unsigned long long fma2(unsigned long long a,
                                                   unsigned long long b,
                                                   unsigned long long c) {
    unsigned long long d;
    asm("fma.rn.f32x2 %0, %1, %2, %3;" : "=l"(d) : "l"(a), "l"(b), "l"(c));
    return d;
}

// ----------------------------- small kernels --------------------------------

// transpose (B,3,N)->(B*N,3) with fused layer-1 sqnorm; one thread per point
__global__ void transpose_sq_kernel(const float* __restrict__ x,
                                    float* __restrict__ xt,
                                    float* __restrict__ sq) {
    int i = blockIdx.x * blockDim.x + threadIdx.x;
    if (i >= NROWS) return;
    int b = i / NPTS, n = i % NPTS;
    const float* xb = x + (size_t)b * 3 * NPTS;
    float v0 = xb[0 * NPTS + n];
    float v1 = xb[1 * NPTS + n];
    float v2 = xb[2 * NPTS + n];
    float* o = xt + (size_t)i * 3;
    o[0] = v0; o[1] = v1; o[2] = v2;
    float s = 0.f;
    s += v0 * v0; s += v1 * v1; s += v2 * v2;
    sq[i] = s;
}

// Build [W_a ; W_b - W_a] for all four layers in one pass.
__global__ void wcomb_all_kernel(const float* __restrict__ W1,
                                 const float* __restrict__ W2,
                                 const float* __restrict__ W3,
                                 const float* __restrict__ W4,
                                 float* __restrict__ Wc) {
    int i = blockIdx.x * blockDim.x + threadIdx.x;
    const int n1 = 2 * 64 * 3, n2 = 2 * 64 * 64, n3 = 2 * 128 * 64, n4 = 2 * 256 * 128;
    const float* W; int C, D, off, li;
    if (i < n1)                { W = W1; C = 64;  D = 3;   off = WCO1; li = i; }
    else if (i < n1+n2)        { W = W2; C = 64;  D = 64;  off = WCO2; li = i - n1; }
    else if (i < n1+n2+n3)     { W = W3; C = 128; D = 64;  off = WCO3; li = i - n1 - n2; }
    else if (i < n1+n2+n3+n4)  { W = W4; C = 256; D = 128; off = WCO4; li = i - n1 - n2 - n3; }
    else return;
    int c = li / D, d = li % D;
    Wc[off + li] = (c < C) ? W[c * 2 * D + d]
                           : (W[(c - C) * 2 * D + D + d] - W[(c - C) * 2 * D + d]);
}

// ----------------------------- GEMM (store modes) ----------------------------
// NT GEMM:  C[m,n] = sum_k A[m,k] * B[n,k]
// MODE 0: plain store ; MODE 1: dist store ;
// MODE 2: bn+lrelu + fused max/mean pooling partials (no C store)
#define TBM 128
#define TBN 128
#define TBK 8

template <int MODE>
__global__ __launch_bounds__(256, 2)
void gemm_nt_kernel(const float* __restrict__ A, int lda, long long sA,
                    const float* __restrict__ Bw, int ldb, long long sB,
                    float* __restrict__ C, int ldc, long long sC,
                    int M, int Nn, int K,
                    const float* __restrict__ sq, long long sSq,
                    const float* __restrict__ gamma, const float* __restrict__ beta,
                    float* __restrict__ pmax, float* __restrict__ psum) {
    int bz = blockIdx.z;
    A  += (long long)bz * sA;
    Bw += (long long)bz * sB;
    if (MODE != 2) C += (long long)bz * sC;
    const float* sqp = (MODE == 1) ? (sq + (long long)bz * sSq) : nullptr;

    __shared__ __align__(16) float As[2][TBK][TBM + 4];
    __shared__ __align__(16) float Bs[2][TBK][TBN + 4];

    const int m0 = blockIdx.y * TBM;
    const int n0 = blockIdx.x * TBN;
    const int tid = threadIdx.x;
    const int tn = tid % 16;
    const int tm = tid / 16;

    float acc[8][8];

    const bool vec = ((lda % 4) == 0) && ((ldb % 4) == 0) && ((K % TBK) == 0);
    const int lr = tid >> 1;
    const int lp = (tid & 1) * 4;

    if (vec) {
        // accumulators packed along i: acc2[p][j] lanes = (acc[2p][j], acc[2p+1][j])
        unsigned long long acc2[4][8];
#pragma unroll
        for (int p = 0; p < 4; ++p)
#pragma unroll
            for (int j = 0; j < 8; ++j) acc2[p][j] = 0ULL;
        {
            float4 va = *(const float4*)(A + (long long)(m0 + lr) * lda + lp);
            float4 vb = *(const float4*)(Bw + (long long)(n0 + lr) * ldb + lp);
            As[0][lp + 0][lr] = va.x; As[0][lp + 1][lr] = va.y;
            As[0][lp + 2][lr] = va.z; As[0][lp + 3][lr] = va.w;
            Bs[0][lp + 0][lr] = vb.x; Bs[0][lp + 1][lr] = vb.y;
            Bs[0][lp + 2][lr] = vb.z; Bs[0][lp + 3][lr] = vb.w;
        }
        __syncthreads();
        int cur = 0;
        for (int k0 = 0; k0 < K; k0 += TBK) {
            const bool has_next = (k0 + TBK) < K;
            float4 na, nb;
            if (has_next) {
                na = *(const float4*)(A + (long long)(m0 + lr) * lda + k0 + TBK + lp);
                nb = *(const float4*)(Bw + (long long)(n0 + lr) * ldb + k0 + TBK + lp);
            }
#pragma unroll
            for (int kk = 0; kk < TBK; ++kk) {
                const ulonglong2* pa = (const ulonglong2*)&As[cur][kk][tm * 8];
                ulonglong2 a01 = pa[0], a23 = pa[1];
                unsigned long long ap[4] = {a01.x, a01.y, a23.x, a23.y};
                const float4* pb = (const float4*)&Bs[cur][kk][tn * 8];
                float4 b0 = pb[0], b1 = pb[1];
                unsigned long long bj[8];
                bj[0] = pack2(b0.x, b0.x); bj[1] = pack2(b0.y, b0.y);
                bj[2] = pack2(b0.z, b0.z); bj[3] = pack2(b0.w, b0.w);
                bj[4] = pack2(b1.x, b1.x); bj[5] = pack2(b1.y, b1.y);
                bj[6] = pack2(b1.z, b1.z); bj[7] = pack2(b1.w, b1.w);
#pragma unroll
                for (int p = 0; p < 4; ++p)
#pragma unroll
                    for (int j = 0; j < 8; ++j)
                        acc2[p][j] = fma2(ap[p], bj[j], acc2[p][j]);
            }
            if (has_next) {
                int nxt = cur ^ 1;
                As[nxt][lp + 0][lr] = na.x; As[nxt][lp + 1][lr] = na.y;
                As[nxt][lp + 2][lr] = na.z; As[nxt][lp + 3][lr] = na.w;
                Bs[nxt][lp + 0][lr] = nb.x; Bs[nxt][lp + 1][lr] = nb.y;
                Bs[nxt][lp + 2][lr] = nb.z; Bs[nxt][lp + 3][lr] = nb.w;
            }
            __syncthreads();
            cur ^= 1;
        }
#pragma unroll
        for (int p = 0; p < 4; ++p)
#pragma unroll
            for (int j = 0; j < 8; ++j)
                unpack2(acc2[p][j], acc[2 * p][j], acc[2 * p + 1][j]);
    } else {
#pragma unroll
        for (int i = 0; i < 8; ++i)
#pragma unroll
            for (int j = 0; j < 8; ++j) acc[i][j] = 0.f;
        for (int k0 = 0; k0 < K; k0 += TBK) {
            for (int i = tid; i < TBM * TBK; i += 256) {
                int mm = i % TBM, kk = i / TBM;
                int gk = k0 + kk;
                As[0][kk][mm] = (gk < K) ? A[(long long)(m0 + mm) * lda + gk] : 0.f;
            }
            for (int i = tid; i < TBN * TBK; i += 256) {
                int nn = i % TBN, kk = i / TBN;
                int gk = k0 + kk;
                Bs[0][kk][nn] = (gk < K) ? Bw[(long long)(n0 + nn) * ldb + gk] : 0.f;
            }
            __syncthreads();
#pragma unroll
            for (int kk = 0; kk < TBK; ++kk) {
                float ra[8], rb[8];
                const float4* pa = (const float4*)&As[0][kk][tm * 8];
                const float4* pb = (const float4*)&Bs[0][kk][tn * 8];
                float4 a0 = pa[0], a1 = pa[1];
                float4 b0 = pb[0], b1 = pb[1];
                ra[0] = a0.x; ra[1] = a0.y; ra[2] = a0.z; ra[3] = a0.w;
                ra[4] = a1.x; ra[5] = a1.y; ra[6] = a1.z; ra[7] = a1.w;
                rb[0] = b0.x; rb[1] = b0.y; rb[2] = b0.z; rb[3] = b0.w;
                rb[4] = b1.x; rb[5] = b1.y; rb[6] = b1.z; rb[7] = b1.w;
#pragma unroll
                for (int i = 0; i < 8; ++i)
#pragma unroll
                    for (int j = 0; j < 8; ++j) acc[i][j] += ra[i] * rb[j];
            }
            __syncthreads();
        }
    }

    if (MODE == 2) {
        float cmax[8], csum[8];
#pragma unroll
        for (int j = 0; j < 8; ++j) { cmax[j] = -FLT_MAX; csum[j] = 0.f; }
#pragma unroll
        for (int i = 0; i < 8; ++i) {
#pragma unroll
            for (int j = 0; j < 8; ++j) {
                int gn = n0 + tn * 8 + j;
                float s = gamma[gn] * rsqrtf(1.0f + EPS_BN);
                float t = acc[i][j] * s + beta[gn];
                t = (t >= 0.f) ? t : SLOPE * t;
                cmax[j] = fmaxf(cmax[j], t);
                csum[j] += t;
            }
        }
        __syncthreads();
        float2 (*red)[TBN] = (float2 (*)[TBN])&As[0][0][0];   // 16KB
#pragma unroll
        for (int j = 0; j < 8; ++j)
            red[tm][tn * 8 + j] = make_float2(cmax[j], csum[j]);
        __syncthreads();
        if (tid < TBN) {
            float mx = -FLT_MAX, sm = 0.f;
#pragma unroll
            for (int g = 0; g < 16; ++g) {
                float2 r = red[g][tid];
                mx = fmaxf(mx, r.x);
                sm += r.y;
            }
            int b = m0 / NPTS;
            int q = (m0 % NPTS) / TBM;
            int gn = n0 + tid;
            pmax[(b * 32 + q) * 512 + gn] = mx;
            psum[(b * 32 + q) * 512 + gn] = sm;
        }
        return;
    }

#pragma unroll
    for (int i = 0; i < 8; ++i) {
        int gm = m0 + tm * 8 + i;
        float* crow = C + (long long)gm * ldc + n0 + tn * 8;
        float v[8];
        if (MODE == 1) {
            float sm = sqp[gm];
#pragma unroll
            for (int j = 0; j < 8; ++j) {
                int gn = n0 + tn * 8 + j;
                v[j] = dist_val(sm, sqp[gn], acc[i][j]);
            }
        } else {
#pragma unroll
            for (int j = 0; j < 8; ++j) v[j] = acc[i][j];
        }
        ((float4*)crow)[0] = make_float4(v[0], v[1], v[2], v[3]);
        ((float4*)crow)[1] = make_float4(v[4], v[5], v[6], v[7]);
    }
}

// ----------------------- symmetric dist filter (triangular) ------------------
__global__ __launch_bounds__(256, 2)
void dist_filter_kernel(const float* __restrict__ X, int lda, int K,
                        const float* __restrict__ sq,
                        const float* __restrict__ thr,
                        int* __restrict__ cnt,
                        unsigned long long* __restrict__ cand) {
    const int bz = blockIdx.z;
    const float* A = X + (long long)bz * NPTS * lda;
    const float* sqp = sq + (long long)bz * NPTS;
    const float* thrp = thr + (long long)bz * NPTS;
    int* cntp = cnt + (long long)bz * NPTS * CNT_STRIDE;
    unsigned long long* candp = cand + (size_t)bz * NPTS * CAND_CAP;

    int t = blockIdx.x, ty = 0;
    while (t >= NT - ty) { t -= NT - ty; ++ty; }
    const int tx = ty + t;
    const int m0 = ty * TBM;
    const int n0 = tx * TBN;
    const bool offdiag = (tx > ty);

    __shared__ __align__(16) float As[2][TBK][TBM + 4];
    __shared__ __align__(16) float Bs[2][TBK][TBN + 4];

    const int tid = threadIdx.x;
    const int lane = tid & 31;
    const int warp = tid >> 5;
    const int wy = warp >> 1;
    const int wx = warp & 1;
    const int ly = lane >> 3;
    const int lx = lane & 7;
    const int row_off = wy * 32 + ly * 8;
    const int col_off = wx * 64 + lx * 8;

    float acc[8][8];

    const bool vec = ((lda % 4) == 0) && ((K % TBK) == 0);
    const int lr = tid >> 1;
    const int lp = (tid & 1) * 4;

    if (vec) {
        unsigned long long acc2[4][8];
#pragma unroll
        for (int p = 0; p < 4; ++p)
#pragma unroll
            for (int j = 0; j < 8; ++j) acc2[p][j] = 0ULL;
        {
            float4 va = *(const float4*)(A + (long long)(m0 + lr) * lda + lp);
            float4 vb = *(const float4*)(A + (long long)(n0 + lr) * lda + lp);
            As[0][lp + 0][lr] = va.x; As[0][lp + 1][lr] = va.y;
            As[0][lp + 2][lr] = va.z; As[0][lp + 3][lr] = va.w;
            Bs[0][lp + 0][lr] = vb.x; Bs[0][lp + 1][lr] = vb.y;
            Bs[0][lp + 2][lr] = vb.z; Bs[0][lp + 3][lr] = vb.w;
        }
        __syncthreads();
        int cur = 0;
        for (int k0 = 0; k0 < K; k0 += TBK) {
            const bool has_next = (k0 + TBK) < K;
            float4 na, nb;
            if (has_next) {
                na = *(const float4*)(A + (long long)(m0 + lr) * lda + k0 + TBK + lp);
                nb = *(const float4*)(A + (long long)(n0 + lr) * lda + k0 + TBK + lp);
            }
#pragma unroll
            for (int kk = 0; kk < TBK; ++kk) {
                const ulonglong2* pa = (const ulonglong2*)&As[cur][kk][row_off];
                ulonglong2 a01 = pa[0], a23 = pa[1];
                unsigned long long ap[4] = {a01.x, a01.y, a23.x, a23.y};
                const float4* pb = (const float4*)&Bs[cur][kk][col_off];
                float4 b0 = pb[0], b1 = pb[1];
                unsigned long long bj[8];
                bj[0] = pack2(b0.x, b0.x); bj[1] = pack2(b0.y, b0.y);
                bj[2] = pack2(b0.z, b0.z); bj[3] = pack2(b0.w, b0.w);
                bj[4] = pack2(b1.x, b1.x); bj[5] = pack2(b1.y, b1.y);
                bj[6] = pack2(b1.z, b1.z); bj[7] = pack2(b1.w, b1.w);
#pragma unroll
                for (int p = 0; p < 4; ++p)
#pragma unroll
                    for (int j = 0; j < 8; ++j)
                        acc2[p][j] = fma2(ap[p], bj[j], acc2[p][j]);
            }
            if (has_next) {
                int nxt = cur ^ 1;
                As[nxt][lp + 0][lr] = na.x; As[nxt][lp + 1][lr] = na.y;
                As[nxt][lp + 2][lr] = na.z; As[nxt][lp + 3][lr] = na.w;
                Bs[nxt][lp + 0][lr] = nb.x; Bs[nxt][lp + 1][lr] = nb.y;
                Bs[nxt][lp + 2][lr] = nb.z; Bs[nxt][lp + 3][lr] = nb.w;
            }
            __syncthreads();
            cur ^= 1;
        }
#pragma unroll
        for (int p = 0; p < 4; ++p)
#pragma unroll
            for (int j = 0; j < 8; ++j)
                unpack2(acc2[p][j], acc[2 * p][j], acc[2 * p + 1][j]);
    } else {
#pragma unroll
        for (int i = 0; i < 8; ++i)
#pragma unroll
            for (int j = 0; j < 8; ++j) acc[i][j] = 0.f;
        for (int k0 = 0; k0 < K; k0 += TBK) {
            for (int i = tid; i < TBM * TBK; i += 256) {
                int mm = i % TBM, kk = i / TBM;
                int gk = k0 + kk;
                As[0][kk][mm] = (gk < K) ? A[(long long)(m0 + mm) * lda + gk] : 0.f;
            }
            for (int i = tid; i < TBN * TBK; i += 256) {
                int nn = i % TBN, kk = i / TBN;
                int gk = k0 + kk;
                Bs[0][kk][nn] = (gk < K) ? A[(long long)(n0 + nn) * lda + gk] : 0.f;
            }
            __syncthreads();
#pragma unroll
            for (int kk = 0; kk < TBK; ++kk) {
                float ra[8], rb[8];
                const float4* pa = (const float4*)&As[0][kk][row_off];
                const float4* pb = (const float4*)&Bs[0][kk][col_off];
                float4 a0 = pa[0], a1 = pa[1];
                float4 b0 = pb[0], b1 = pb[1];
                ra[0] = a0.x; ra[1] = a0.y; ra[2] = a0.z; ra[3] = a0.w;
                ra[4] = a1.x; ra[5] = a1.y; ra[6] = a1.z; ra[7] = a1.w;
                rb[0] = b0.x; rb[1] = b0.y; rb[2] = b0.z; rb[3] = b0.w;
                rb[4] = b1.x; rb[5] = b1.y; rb[6] = b1.z; rb[7] = b1.w;
#pragma unroll
                for (int i = 0; i < 8; ++i)
#pragma unroll
                    for (int j = 0; j < 8; ++j) acc[i][j] += ra[i] * rb[j];
            }
            __syncthreads();
        }
    }

    float sm[8], sn[8], trr[8], trc[8];
#pragma unroll
    for (int i = 0; i < 8; ++i) {
        sm[i] = sqp[m0 + row_off + i];
        trr[i] = thrp[m0 + row_off + i];
    }
#pragma unroll
    for (int j = 0; j < 8; ++j) {
        sn[j] = sqp[n0 + col_off + j];
        trc[j] = thrp[n0 + col_off + j];
    }
#pragma unroll
    for (int i = 0; i < 8; ++i)
#pragma unroll
        for (int j = 0; j < 8; ++j)
            acc[i][j] = dist_val(sm[i], sn[j], acc[i][j]);

    // ---- row push: 8-lane groups (ly fixed), leader lane = ly*8 ----
    {
        const unsigned grp = 0xFFu << (ly * 8);
        const unsigned below = ((1u << lx) - 1u) << (ly * 8);
        const int leader_lane = ly * 8;
#pragma unroll
        for (int i = 0; i < 8; ++i) {
            const int gm = m0 + row_off + i;
            unsigned pb[8];
            int rank[8];
            int cum = 0;
#pragma unroll
            for (int j = 0; j < 8; ++j) {
                unsigned ball = __ballot_sync(0xFFFFFFFFu, acc[i][j] <= trr[i]) & grp;
                rank[j] = cum + __popc(ball & below);
                cum += __popc(ball);
                pb[j] = ball;
            }
            int base = 0;
            if (lx == 0 && cum > 0) base = atomicAdd(&cntp[gm * CNT_STRIDE], cum);
            base = __shfl_sync(0xFFFFFFFFu, base, leader_lane);
            if (cum > 0) {
                unsigned long long* dst = candp + (size_t)gm * CAND_CAP;
#pragma unroll
                for (int j = 0; j < 8; ++j) {
                    if (pb[j] & (1u << lane)) {
                        int pos = base + rank[j];
                        if (pos < CAND_CAP) {
                            int gn = n0 + col_off + j;
                            dst[pos] = ((unsigned long long)float_key(acc[i][j]) << 32)
                                       | (unsigned int)gn;
                        }
                    }
                }
            }
        }
    }

    // ---- col push (off-diagonal only): 4-lane strided groups (lx fixed) ----
    if (offdiag) {
        const unsigned grp = 0x01010101u << lx;
        const unsigned below = grp & ((1u << lane) - 1u);
        const int leader_lane = lx;
#pragma unroll
        for (int j = 0; j < 8; ++j) {
            const int gn = n0 + col_off + j;
            unsigned pb[8];
            int rank[8];
            int cum = 0;
#pragma unroll
            for (int i = 0; i < 8; ++i) {
                unsigned ball = __ballot_sync(0xFFFFFFFFu, acc[i][j] <= trc[j]) & grp;
                rank[i] = cum + __popc(ball & below);
                cum += __popc(ball);
                pb[i] = ball;
            }
            int base = 0;
            if (ly == 0 && cum > 0) base = atomicAdd(&cntp[gn * CNT_STRIDE], cum);
            base = __shfl_sync(0xFFFFFFFFu, base, leader_lane);
            if (cum > 0) {
                unsigned long long* dst = candp + (size_t)gn * CAND_CAP;
#pragma unroll
                for (int i = 0; i < 8; ++i) {
                    if (pb[i] & (1u << lane)) {
                        int pos = base + rank[i];
                        if (pos < CAND_CAP) {
                            int gm = m0 + row_off + i;
                            dst[pos] = ((unsigned long long)float_key(acc[i][j]) << 32)
                                       | (unsigned int)gm;
                        }
                    }
                }
            }
        }
    }
}

// ----------------------------- threshold from subset -------------------------
__global__ __launch_bounds__(256)
void thr_kernel(const float* __restrict__ sd, float* __restrict__ thr,
                int* __restrict__ cnt) {
    int warp = (blockIdx.x * blockDim.x + threadIdx.x) >> 5;
    int lane = threadIdx.x & 31;
    if (warp >= NROWS) return;
    const float4* row4 = (const float4*)(sd + (size_t)warp * NSUB);

    float loc[KNN];
#pragma unroll
    for (int t = 0; t < KNN; ++t) loc[t] = FLT_MAX;

#pragma unroll
    for (int g = 0; g < 2; ++g) {
        float4 v4 = row4[g * 32 + lane];
        float vals[4] = {v4.x, v4.y, v4.z, v4.w};
#pragma unroll
        for (int s = 0; s < 4; ++s) {
            float v = vals[s];
#pragma unroll
            for (int t = 0; t < KNN; ++t) {
                float mn = fminf(loc[t], v);
                v = fmaxf(loc[t], v);
                loc[t] = mn;
            }
        }
    }

    float thr_f = 0.f;
#pragma unroll
    for (int s = 0; s < KNN; ++s) {
        float v = loc[0];
#pragma unroll
        for (int off = 16; off > 0; off >>= 1)
            v = fminf(v, __shfl_xor_sync(0xFFFFFFFFu, v, off));
        unsigned m = __ballot_sync(0xFFFFFFFFu, loc[0] == v);
        int wlane = __ffs(m) - 1;
        if (lane == wlane) {
#pragma unroll
            for (int t = 0; t < KNN - 1; ++t) loc[t] = loc[t + 1];
            loc[KNN - 1] = FLT_MAX;
        }
        thr_f = v;
    }
    if (lane == 0) {
        thr[warp] = thr_f;
        cnt[warp * CNT_STRIDE] = 0;
    }
}

// -------------- fused: top-20 select + gather + bn/lrelu + sqnorm ------------
// C==64: lane pairs (l, l+16) share channel-quad l&15 and split the 20
// neighbors 10/10 (exact max, merged via shfl_xor) -> no idle half-warp.
__global__ __launch_bounds__(256)
void topk_gather_kernel(const unsigned long long* __restrict__ cand,
                        const int* __restrict__ cnt,
                        const float* __restrict__ PQ,
                        const float* __restrict__ gamma,
                        const float* __restrict__ beta,
                        float* __restrict__ out, int outLd, int C,
                        float* __restrict__ sqout) {
    __shared__ int sidx[8][KNN];
    const int warp = threadIdx.x >> 5;
    const int lane = threadIdx.x & 31;
    const int point = blockIdx.x * 8 + warp;
    const int b = point / NPTS;

    // ---- phase 1: top-20 selection ----
    {
        int c = cnt[point * CNT_STRIDE];
        if (c > CAND_CAP) c = CAND_CAP;
        const unsigned long long* buf = cand + (size_t)point * CAND_CAP;
        const unsigned long long SENT = 0xFFFFFFFFFFFFFFFFULL;
        unsigned long long loc[KNN];
#pragma unroll
        for (int t = 0; t < KNN; ++t) loc[t] = SENT;
        for (int i = lane; i < c; i += 32) chain_insert20(loc, buf[i]);

#pragma unroll
        for (int s = 0; s < KNN; ++s) {
            unsigned long long v = loc[0];
            int wl = lane;
#pragma unroll
            for (int off = 16; off > 0; off >>= 1) {
                unsigned long long ov = __shfl_down_sync(0xFFFFFFFFu, v, off);
                int owl = __shfl_down_sync(0xFFFFFFFFu, wl, off);
                if (ov < v) { v = ov; wl = owl; }
            }
            unsigned long long win = __shfl_sync(0xFFFFFFFFu, v, 0);
            int wlane = __shfl_sync(0xFFFFFFFFu, wl, 0);
            if (lane == 0) sidx[warp][s] = (int)(win & 0xFFFFFFFFu);
            if (lane == wlane) {
#pragma unroll
                for (int t = 0; t < KNN - 1; ++t) loc[t] = loc[t + 1];
                loc[KNN - 1] = SENT;
            }
        }
        __syncwarp();
    }

    // ---- phase 2: gather + epilogue + sqnorm ----
    const int ld = 2 * C;
    const float4* qrow = (const float4*)(PQ + (size_t)point * ld + C);
    float4* orow = (float4*)(out + (size_t)point * outLd);
    const size_t rowbase = (size_t)b * NPTS;
    const float rs = rsqrtf(1.0f + EPS_BN);
    float ss = 0.f;

    if (C == 64) {
        // pairwise split: c4 = lane&15, neighbors [half*10, half*10+10)
        const int c4 = lane & 15;
        const int half = lane >> 4;
        float4 m = make_float4(-FLT_MAX, -FLT_MAX, -FLT_MAX, -FLT_MAX);
        const int j0 = half * 10;
#pragma unroll
        for (int jj = 0; jj < 10; ++jj) {
            const float4* prow = (const float4*)(PQ + (rowbase + sidx[warp][j0 + jj]) * ld);
            float4 pv = prow[c4];
            m.x = fmaxf(m.x, pv.x); m.y = fmaxf(m.y, pv.y);
            m.z = fmaxf(m.z, pv.z); m.w = fmaxf(m.w, pv.w);
        }
        m.x = fmaxf(m.x, __shfl_xor_sync(0xFFFFFFFFu, m.x, 16));
        m.y = fmaxf(m.y, __shfl_xor_sync(0xFFFFFFFFu, m.y, 16));
        m.z = fmaxf(m.z, __shfl_xor_sync(0xFFFFFFFFu, m.z, 16));
        m.w = fmaxf(m.w, __shfl_xor_sync(0xFFFFFFFFu, m.w, 16));
        if (half == 0) {
            float4 q = qrow[c4];
            float4 gg = ((const float4*)gamma)[c4];
            float4 bb = ((const float4*)beta)[c4];
            float4 v;
            v.x = (m.x + q.x) * (gg.x * rs) + bb.x;
            v.y = (m.y + q.y) * (gg.y * rs) + bb.y;
            v.z = (m.z + q.z) * (gg.z * rs) + bb.z;
            v.w = (m.w + q.w) * (gg.w * rs) + bb.w;
            v.x = (v.x >= 0.f) ? v.x : SLOPE * v.x;
            v.y = (v.y >= 0.f) ? v.y : SLOPE * v.y;
            v.z = (v.z >= 0.f) ? v.z : SLOPE * v.z;
            v.w = (v.w >= 0.f) ? v.w : SLOPE * v.w;
            orow[c4] = v;
            ss = v.x * v.x + v.y * v.y + v.z * v.z + v.w * v.w;
        }
    } else {
        for (int c4 = lane; c4 < C / 4; c4 += 32) {
            float4 m = make_float4(-FLT_MAX, -FLT_MAX, -FLT_MAX, -FLT_MAX);
#pragma unroll 4
            for (int j = 0; j < KNN; ++j) {
                const float4* prow = (const float4*)(PQ + (rowbase + sidx[warp][j]) * ld);
                float4 pv = prow[c4];
                m.x = fmaxf(m.x, pv.x); m.y = fmaxf(m.y, pv.y);
                m.z = fmaxf(m.z, pv.z); m.w = fmaxf(m.w, pv.w);
            }
            float4 q = qrow[c4];
            float4 gg = ((const float4*)gamma)[c4];
            float4 bb = ((const float4*)beta)[c4];
            float4 v;
            v.x = (m.x + q.x) * (gg.x * rs) + bb.x;
            v.y = (m.y + q.y) * (gg.y * rs) + bb.y;
            v.z = (m.z + q.z) * (gg.z * rs) + bb.z;
            v.w = (m.w + q.w) * (gg.w * rs) + bb.w;
            v.x = (v.x >= 0.f) ? v.x : SLOPE * v.x;
            v.y = (v.y >= 0.f) ? v.y : SLOPE * v.y;
            v.z = (v.z >= 0.f) ? v.z : SLOPE * v.z;
            v.w = (v.w >= 0.f) ? v.w : SLOPE * v.w;
            orow[c4] = v;
            ss += v.x * v.x + v.y * v.y + v.z * v.z + v.w * v.w;
        }
    }
#pragma unroll
    for (int off = 16; off > 0; off >>= 1)
        ss += __shfl_down_sync(0xFFFFFFFFu, ss, off);
    if (lane == 0) sqout[point] = ss;
}

// ----------------------------- final pool merge -------------------------------
#define PCHUNK 32

__global__ void reduce2_kernel(const float* __restrict__ pmax,
                               const float* __restrict__ psum,
                               float* __restrict__ out) {
    int b = blockIdx.x;
    int c = threadIdx.x;
    float mx = -FLT_MAX, sm = 0.f;
#pragma unroll
    for (int q = 0; q < PCHUNK; ++q) {
        mx = fmaxf(mx, pmax[(b * PCHUNK + q) * 512 + c]);
        sm += psum[(b * PCHUNK + q) * 512 + c];
    }
    out[b * 1024 + c]       = mx;
    out[b * 1024 + 512 + c] = sm * (1.0f / NPTS);
}

// ----------------------------- host driver ----------------------------------

static void run_edge_conv(const float* X, int lda, int D, int C,
                          const float* g, const float* b,
                          float* h_out_col,
                          float* p_sq, float* p_sub, float* p_thr, int* p_cnt,
                          unsigned long long* p_cand,
                          float* p_PQ, const float* p_wc) {
    // subset dist: every point vs first NSUB points of its batch
    dim3 gs(NSUB / TBN, NPTS / TBM, BATCH);
    gemm_nt_kernel<1><<<gs, 256>>>(X, lda, (long long)NPTS * lda,
                                   X, lda, (long long)NPTS * lda,
                                   p_sub, NSUB, (long long)NPTS * NSUB,
                                   NPTS, NSUB, D,
                                   p_sq, NPTS, nullptr, nullptr,
                                   nullptr, nullptr);

    thr_kernel<<<NROWS / 8, 256>>>(p_sub, p_thr, p_cnt);

    // symmetric triangular filter (no dist store)
    dim3 gd(NPAIRS, 1, BATCH);
    dist_filter_kernel<<<gd, 256>>>(X, lda, D, p_sq, p_thr, p_cnt, p_cand);

    dim3 gp((2 * C) / TBN, NROWS / TBM, 1);
    gemm_nt_kernel<0><<<gp, 256>>>(X, lda, 0, p_wc, D, 0,
                                   p_PQ, 2 * C, 0, NROWS, 2 * C, D,
                                   nullptr, 0, nullptr, nullptr,
                                   nullptr, nullptr);

    // fused top-20 + gather + bn/lrelu + sqnorm for the next layer
    topk_gather_kernel<<<NROWS / 8, 256>>>(p_cand, p_cnt, p_PQ, g, b,
                                           h_out_col, 512, C, p_sq);
}

extern "C" void kernel_launch(void* const* d_in, const int* in_sizes, int n_in,
                              void* d_out, int out_size) {
    const float* x = (const float*)d_in[0];
    int wb = 1;
    if (n_in > 1 && in_sizes[1] == 1) wb = 2;

    const float* W1 = (const float*)d_in[wb + 0];
    const float* g1 = (const float*)d_in[wb + 1];
    const float* b1 = (const float*)d_in[wb + 2];
    const float* W2 = (const float*)d_in[wb + 3];
    const float* g2 = (const float*)d_in[wb + 4];
    const float* b2 = (const float*)d_in[wb + 5];
    const float* W3 = (const float*)d_in[wb + 6];
    const float* g3 = (const float*)d_in[wb + 7];
    const float* b3 = (const float*)d_in[wb + 8];
    const float* W4 = (const float*)d_in[wb + 9];
    const float* g4 = (const float*)d_in[wb + 10];
    const float* b4 = (const float*)d_in[wb + 11];
    const float* W5 = (const float*)d_in[wb + 12];
    const float* g5 = (const float*)d_in[wb + 13];
    const float* b5 = (const float*)d_in[wb + 14];

    void *p;
    cudaGetSymbolAddress(&p, g_x0);    float* x0   = (float*)p;
    cudaGetSymbolAddress(&p, g_h);     float* h    = (float*)p;
    cudaGetSymbolAddress(&p, g_sq);    float* sq   = (float*)p;
    cudaGetSymbolAddress(&p, g_PQ);    float* PQ   = (float*)p;
    cudaGetSymbolAddress(&p, g_wcomb); float* wc   = (float*)p;
    cudaGetSymbolAddress(&p, g_sub);   float* sub  = (float*)p;
    cudaGetSymbolAddress(&p, g_thr);   float* thr  = (float*)p;
    cudaGetSymbolAddress(&p, g_cnt);   int*   cnt  = (int*)p;
    cudaGetSymbolAddress(&p, g_cand);  unsigned long long* cand = (unsigned long long*)p;
    cudaGetSymbolAddress(&p, g_pmax);  float* pmax = (float*)p;
    cudaGetSymbolAddress(&p, g_psum);  float* psum = (float*)p;

    transpose_sq_kernel<<<(NROWS + 255) / 256, 256>>>(x, x0, sq);
    {
        int total = 2 * (64 * 3 + 64 * 64 + 128 * 64 + 256 * 128);
        wcomb_all_kernel<<<(total + 255) / 256, 256>>>(W1, W2, W3, W4, wc);
    }

    run_edge_conv(x0,      3,   3,   64,  g1, b1, h + 0,   sq, sub, thr, cnt, cand, PQ, wc + WCO1);
    run_edge_conv(h + 0,   512, 64,  64,  g2, b2, h + 64,  sq, sub, thr, cnt, cand, PQ, wc + WCO2);
    run_edge_conv(h + 64,  512, 64,  128, g3, b3, h + 128, sq, sub, thr, cnt, cand, PQ, wc + WCO3);
    run_edge_conv(h + 128, 512, 128, 256, g4, b4, h + 256, sq, sub, thr, cnt, cand, PQ, wc + WCO4);

    // final 1x1 conv (512->512): bn+lrelu + pooling partials fused, no y store
    dim3 gf(512 / TBN, NROWS / TBM, 1);
    gemm_nt_kernel<2><<<gf, 256>>>(h, 512, 0, W5, 512, 0,
                                   nullptr, 0, 0, NROWS, 512, 512,
                                   nullptr, 0, g5, b5,
                                   pmax, psum);

    reduce2_kernel<<<BATCH, 512>>>(pmax, psum, (float*)d_out);
}

// round 17
// speedup vs baseline: 1.0119x; 1.0031x over previous
#include <cuda_runtime.h>
#include <cuda_bf16.h>
#include <float.h>

// ---------------------------------------------------------------------------
// DGCNN forward, restructured:
//   EdgeConv(X, W, g, b):  P = X W_a^T ; Q = X (W_b - W_a)^T
//   out[n,c] = bn_lrelu( max_j P[knn(n,j), c] + Q[n,c] )
// kNN via threshold-first filtering (dist matrix never materialized).
// Threshold source: layer 1 = 256-point subset 20th; layers 2-4 = max distance
// to the PREVIOUS layer's 20 neighbors (bitwise-consistent fma chain -> exact
// upper bound on the true 20th-NN distance).
// GEMM inner loops: packed fp32 FMA (fma.rn.f32x2), TBK=8 double-buffered.
// Final GEMM fuses bn+lrelu and the global max/mean pooling partials.
// ---------------------------------------------------------------------------

#define BATCH 8
#define NPTS  4096
#define KNN   20
#define NROWS (BATCH * NPTS)   // 32768
#define EPS_BN 1e-5f
#define SLOPE 0.2f
#define NSUB  256
#define CAND_CAP 2048
#define CNT_STRIDE 8           // 32B padding between counters
#define NT 32                  // 4096/128 tiles per side
#define NPAIRS (NT * (NT + 1) / 2)   // 528

// ----------------------------- scratch (device globals) --------------------
__device__ float g_x0[NROWS * 3];
__device__ float g_h[(size_t)NROWS * 512];
__device__ float g_sq[NROWS];
__device__ int   g_idx[NROWS * KNN];              // per-layer kNN indices
__device__ float g_PQ[(size_t)NROWS * 512];
__device__ float g_wcomb[131072];                 // all layers' [W_a ; W_b-W_a]
__device__ float g_sub[(size_t)NROWS * NSUB];     // subset-dist scratch (layer 1)
__device__ float g_thr[NROWS];
__device__ int   g_cnt[NROWS * CNT_STRIDE];
__device__ unsigned long long g_cand[(size_t)NROWS * CAND_CAP];
__device__ float g_pmax[BATCH * 32 * 512];
__device__ float g_psum[BATCH * 32 * 512];

// per-layer offsets into g_wcomb (2C*D each)
#define WCO1 0
#define WCO2 (WCO1 + 2 * 64 * 3)
#define WCO3 (WCO2 + 2 * 64 * 64)
#define WCO4 (WCO3 + 2 * 128 * 64)

// ----------------------------- helpers ---------------------------------------

__device__ __forceinline__ unsigned int float_key(float f) {
    unsigned int b = __float_as_uint(f);
    unsigned int mask = (unsigned int)(((int)b) >> 31) | 0x80000000u;
    return b ^ mask;   // monotone: smaller float -> smaller uint
}
// Identical FP sequence everywhere a distance is formed (no reassociation).
__device__ __forceinline__ float dist_val(float sm, float sn, float acc) {
    return __fmaf_rn(-2.0f, acc, __fadd_rn(sm, sn));
}
__device__ __forceinline__ void chain_insert20(unsigned long long loc[KNN],
                                               unsigned long long v) {
#pragma unroll
    for (int t = 0; t < KNN; ++t) {
        if (v < loc[t]) { unsigned long long tmp = loc[t]; loc[t] = v; v = tmp; }
    }
}

// packed f32x2 ops (Blackwell): each lane is an exact rn fp32 FMA
__device__ __forceinline__ unsigned long long pack2(float lo, float hi) {
    unsigned long long d;
    asm("mov.b64 %0, {%1, %2};" : "=l"(d) : "r"(__float_as_uint(lo)), "r"(__float_as_uint(hi)));
    return d;
}
__device__ __forceinline__ void unpack2(unsigned long long v, float& lo, float& hi) {
    unsigned int a, b;
    asm("mov.b64 {%0, %1}, %2;" : "=r"(a), "=r"(b) : "l"(v));
    lo = __uint_as_float(a);
    hi = __uint_as_float(b);
}
__device__ __forceinline__ unsigned long long fma2(unsigned long long a,
                                                   unsigned long long b,
                                                   unsigned long long c) {
    unsigned long long d;
    asm("fma.rn.f32x2 %0, %1, %2, %3;" : "=l"(d) : "l"(a), "l"(b), "l"(c));
    return d;
}

// ----------------------------- small kernels --------------------------------

// transpose (B,3,N)->(B*N,3) with fused layer-1 sqnorm; one thread per point
__global__ void transpose_sq_kernel(const float* __restrict__ x,
                                    float* __restrict__ xt,
                                    float* __restrict__ sq) {
    int i = blockIdx.x * blockDim.x + threadIdx.x;
    if (i >= NROWS) return;
    int b = i / NPTS, n = i % NPTS;
    const float* xb = x + (size_t)b * 3 * NPTS;
    float v0 = xb[0 * NPTS + n];
    float v1 = xb[1 * NPTS + n];
    float v2 = xb[2 * NPTS + n];
    float* o = xt + (size_t)i * 3;
    o[0] = v0; o[1] = v1; o[2] = v2;
    float s = 0.f;
    s += v0 * v0; s += v1 * v1; s += v2 * v2;
    sq[i] = s;
}

// Build [W_a ; W_b - W_a] for all four layers in one pass.
__global__ void wcomb_all_kernel(const float* __restrict__ W1,
                                 const float* __restrict__ W2,
                                 const float* __restrict__ W3,
                                 const float* __restrict__ W4,
                                 float* __restrict__ Wc) {
    int i = blockIdx.x * blockDim.x + threadIdx.x;
    const int n1 = 2 * 64 * 3, n2 = 2 * 64 * 64, n3 = 2 * 128 * 64, n4 = 2 * 256 * 128;
    const float* W; int C, D, off, li;
    if (i < n1)                { W = W1; C = 64;  D = 3;   off = WCO1; li = i; }
    else if (i < n1+n2)        { W = W2; C = 64;  D = 64;  off = WCO2; li = i - n1; }
    else if (i < n1+n2+n3)     { W = W3; C = 128; D = 64;  off = WCO3; li = i - n1 - n2; }
    else if (i < n1+n2+n3+n4)  { W = W4; C = 256; D = 128; off = WCO4; li = i - n1 - n2 - n3; }
    else return;
    int c = li / D, d = li % D;
    Wc[off + li] = (c < C) ? W[c * 2 * D + d]
                           : (W[(c - C) * 2 * D + D + d] - W[(c - C) * 2 * D + d]);
}

// ----------------------------- GEMM (store modes) ----------------------------
// NT GEMM:  C[m,n] = sum_k A[m,k] * B[n,k]
// MODE 0: plain store ; MODE 1: dist store ;
// MODE 2: bn+lrelu + fused max/mean pooling partials (no C store)
#define TBM 128
#define TBN 128
#define TBK 8

template <int MODE>
__global__ __launch_bounds__(256, 2)
void gemm_nt_kernel(const float* __restrict__ A, int lda, long long sA,
                    const float* __restrict__ Bw, int ldb, long long sB,
                    float* __restrict__ C, int ldc, long long sC,
                    int M, int Nn, int K,
                    const float* __restrict__ sq, long long sSq,
                    const float* __restrict__ gamma, const float* __restrict__ beta,
                    float* __restrict__ pmax, float* __restrict__ psum) {
    int bz = blockIdx.z;
    A  += (long long)bz * sA;
    Bw += (long long)bz * sB;
    if (MODE != 2) C += (long long)bz * sC;
    const float* sqp = (MODE == 1) ? (sq + (long long)bz * sSq) : nullptr;

    __shared__ __align__(16) float As[2][TBK][TBM + 4];
    __shared__ __align__(16) float Bs[2][TBK][TBN + 4];

    const int m0 = blockIdx.y * TBM;
    const int n0 = blockIdx.x * TBN;
    const int tid = threadIdx.x;
    const int tn = tid % 16;
    const int tm = tid / 16;

    float acc[8][8];

    const bool vec = ((lda % 4) == 0) && ((ldb % 4) == 0) && ((K % TBK) == 0);
    const int lr = tid >> 1;
    const int lp = (tid & 1) * 4;

    if (vec) {
        unsigned long long acc2[4][8];
#pragma unroll
        for (int p = 0; p < 4; ++p)
#pragma unroll
            for (int j = 0; j < 8; ++j) acc2[p][j] = 0ULL;
        {
            float4 va = *(const float4*)(A + (long long)(m0 + lr) * lda + lp);
            float4 vb = *(const float4*)(Bw + (long long)(n0 + lr) * ldb + lp);
            As[0][lp + 0][lr] = va.x; As[0][lp + 1][lr] = va.y;
            As[0][lp + 2][lr] = va.z; As[0][lp + 3][lr] = va.w;
            Bs[0][lp + 0][lr] = vb.x; Bs[0][lp + 1][lr] = vb.y;
            Bs[0][lp + 2][lr] = vb.z; Bs[0][lp + 3][lr] = vb.w;
        }
        __syncthreads();
        int cur = 0;
        for (int k0 = 0; k0 < K; k0 += TBK) {
            const bool has_next = (k0 + TBK) < K;
            float4 na, nb;
            if (has_next) {
                na = *(const float4*)(A + (long long)(m0 + lr) * lda + k0 + TBK + lp);
                nb = *(const float4*)(Bw + (long long)(n0 + lr) * ldb + k0 + TBK + lp);
            }
#pragma unroll
            for (int kk = 0; kk < TBK; ++kk) {
                const ulonglong2* pa = (const ulonglong2*)&As[cur][kk][tm * 8];
                ulonglong2 a01 = pa[0], a23 = pa[1];
                unsigned long long ap[4] = {a01.x, a01.y, a23.x, a23.y};
                const float4* pb = (const float4*)&Bs[cur][kk][tn * 8];
                float4 b0 = pb[0], b1 = pb[1];
                unsigned long long bj[8];
                bj[0] = pack2(b0.x, b0.x); bj[1] = pack2(b0.y, b0.y);
                bj[2] = pack2(b0.z, b0.z); bj[3] = pack2(b0.w, b0.w);
                bj[4] = pack2(b1.x, b1.x); bj[5] = pack2(b1.y, b1.y);
                bj[6] = pack2(b1.z, b1.z); bj[7] = pack2(b1.w, b1.w);
#pragma unroll
                for (int p = 0; p < 4; ++p)
#pragma unroll
                    for (int j = 0; j < 8; ++j)
                        acc2[p][j] = fma2(ap[p], bj[j], acc2[p][j]);
            }
            if (has_next) {
                int nxt = cur ^ 1;
                As[nxt][lp + 0][lr] = na.x; As[nxt][lp + 1][lr] = na.y;
                As[nxt][lp + 2][lr] = na.z; As[nxt][lp + 3][lr] = na.w;
                Bs[nxt][lp + 0][lr] = nb.x; Bs[nxt][lp + 1][lr] = nb.y;
                Bs[nxt][lp + 2][lr] = nb.z; Bs[nxt][lp + 3][lr] = nb.w;
            }
            __syncthreads();
            cur ^= 1;
        }
#pragma unroll
        for (int p = 0; p < 4; ++p)
#pragma unroll
            for (int j = 0; j < 8; ++j)
                unpack2(acc2[p][j], acc[2 * p][j], acc[2 * p + 1][j]);
    } else {
#pragma unroll
        for (int i = 0; i < 8; ++i)
#pragma unroll
            for (int j = 0; j < 8; ++j) acc[i][j] = 0.f;
        for (int k0 = 0; k0 < K; k0 += TBK) {
            for (int i = tid; i < TBM * TBK; i += 256) {
                int mm = i % TBM, kk = i / TBM;
                int gk = k0 + kk;
                As[0][kk][mm] = (gk < K) ? A[(long long)(m0 + mm) * lda + gk] : 0.f;
            }
            for (int i = tid; i < TBN * TBK; i += 256) {
                int nn = i % TBN, kk = i / TBN;
                int gk = k0 + kk;
                Bs[0][kk][nn] = (gk < K) ? Bw[(long long)(n0 + nn) * ldb + gk] : 0.f;
            }
            __syncthreads();
#pragma unroll
            for (int kk = 0; kk < TBK; ++kk) {
                float ra[8], rb[8];
                const float4* pa = (const float4*)&As[0][kk][tm * 8];
                const float4* pb = (const float4*)&Bs[0][kk][tn * 8];
                float4 a0 = pa[0], a1 = pa[1];
                float4 b0 = pb[0], b1 = pb[1];
                ra[0] = a0.x; ra[1] = a0.y; ra[2] = a0.z; ra[3] = a0.w;
                ra[4] = a1.x; ra[5] = a1.y; ra[6] = a1.z; ra[7] = a1.w;
                rb[0] = b0.x; rb[1] = b0.y; rb[2] = b0.z; rb[3] = b0.w;
                rb[4] = b1.x; rb[5] = b1.y; rb[6] = b1.z; rb[7] = b1.w;
#pragma unroll
                for (int i = 0; i < 8; ++i)
#pragma unroll
                    for (int j = 0; j < 8; ++j) acc[i][j] += ra[i] * rb[j];
            }
            __syncthreads();
        }
    }

    if (MODE == 2) {
        float cmax[8], csum[8];
#pragma unroll
        for (int j = 0; j < 8; ++j) { cmax[j] = -FLT_MAX; csum[j] = 0.f; }
#pragma unroll
        for (int i = 0; i < 8; ++i) {
#pragma unroll
            for (int j = 0; j < 8; ++j) {
                int gn = n0 + tn * 8 + j;
                float s = gamma[gn] * rsqrtf(1.0f + EPS_BN);
                float t = acc[i][j] * s + beta[gn];
                t = (t >= 0.f) ? t : SLOPE * t;
                cmax[j] = fmaxf(cmax[j], t);
                csum[j] += t;
            }
        }
        __syncthreads();
        float2 (*red)[TBN] = (float2 (*)[TBN])&As[0][0][0];   // 16KB
#pragma unroll
        for (int j = 0; j < 8; ++j)
            red[tm][tn * 8 + j] = make_float2(cmax[j], csum[j]);
        __syncthreads();
        if (tid < TBN) {
            float mx = -FLT_MAX, sm = 0.f;
#pragma unroll
            for (int g = 0; g < 16; ++g) {
                float2 r = red[g][tid];
                mx = fmaxf(mx, r.x);
                sm += r.y;
            }
            int b = m0 / NPTS;
            int q = (m0 % NPTS) / TBM;
            int gn = n0 + tid;
            pmax[(b * 32 + q) * 512 + gn] = mx;
            psum[(b * 32 + q) * 512 + gn] = sm;
        }
        return;
    }

#pragma unroll
    for (int i = 0; i < 8; ++i) {
        int gm = m0 + tm * 8 + i;
        float* crow = C + (long long)gm * ldc + n0 + tn * 8;
        float v[8];
        if (MODE == 1) {
            float sm = sqp[gm];
#pragma unroll
            for (int j = 0; j < 8; ++j) {
                int gn = n0 + tn * 8 + j;
                v[j] = dist_val(sm, sqp[gn], acc[i][j]);
            }
        } else {
#pragma unroll
            for (int j = 0; j < 8; ++j) v[j] = acc[i][j];
        }
        ((float4*)crow)[0] = make_float4(v[0], v[1], v[2], v[3]);
        ((float4*)crow)[1] = make_float4(v[4], v[5], v[6], v[7]);
    }
}

// ----------------------- symmetric dist filter (triangular) ------------------
__global__ __launch_bounds__(256, 2)
void dist_filter_kernel(const float* __restrict__ X, int lda, int K,
                        const float* __restrict__ sq,
                        const float* __restrict__ thr,
                        int* __restrict__ cnt,
                        unsigned long long* __restrict__ cand) {
    const int bz = blockIdx.z;
    const float* A = X + (long long)bz * NPTS * lda;
    const float* sqp = sq + (long long)bz * NPTS;
    const float* thrp = thr + (long long)bz * NPTS;
    int* cntp = cnt + (long long)bz * NPTS * CNT_STRIDE;
    unsigned long long* candp = cand + (size_t)bz * NPTS * CAND_CAP;

    int t = blockIdx.x, ty = 0;
    while (t >= NT - ty) { t -= NT - ty; ++ty; }
    const int tx = ty + t;
    const int m0 = ty * TBM;
    const int n0 = tx * TBN;
    const bool offdiag = (tx > ty);

    __shared__ __align__(16) float As[2][TBK][TBM + 4];
    __shared__ __align__(16) float Bs[2][TBK][TBN + 4];

    const int tid = threadIdx.x;
    const int lane = tid & 31;
    const int warp = tid >> 5;
    const int wy = warp >> 1;
    const int wx = warp & 1;
    const int ly = lane >> 3;
    const int lx = lane & 7;
    const int row_off = wy * 32 + ly * 8;
    const int col_off = wx * 64 + lx * 8;

    float acc[8][8];

    const bool vec = ((lda % 4) == 0) && ((K % TBK) == 0);
    const int lr = tid >> 1;
    const int lp = (tid & 1) * 4;

    if (vec) {
        unsigned long long acc2[4][8];
#pragma unroll
        for (int p = 0; p < 4; ++p)
#pragma unroll
            for (int j = 0; j < 8; ++j) acc2[p][j] = 0ULL;
        {
            float4 va = *(const float4*)(A + (long long)(m0 + lr) * lda + lp);
            float4 vb = *(const float4*)(A + (long long)(n0 + lr) * lda + lp);
            As[0][lp + 0][lr] = va.x; As[0][lp + 1][lr] = va.y;
            As[0][lp + 2][lr] = va.z; As[0][lp + 3][lr] = va.w;
            Bs[0][lp + 0][lr] = vb.x; Bs[0][lp + 1][lr] = vb.y;
            Bs[0][lp + 2][lr] = vb.z; Bs[0][lp + 3][lr] = vb.w;
        }
        __syncthreads();
        int cur = 0;
        for (int k0 = 0; k0 < K; k0 += TBK) {
            const bool has_next = (k0 + TBK) < K;
            float4 na, nb;
            if (has_next) {
                na = *(const float4*)(A + (long long)(m0 + lr) * lda + k0 + TBK + lp);
                nb = *(const float4*)(A + (long long)(n0 + lr) * lda + k0 + TBK + lp);
            }
#pragma unroll
            for (int kk = 0; kk < TBK; ++kk) {
                const ulonglong2* pa = (const ulonglong2*)&As[cur][kk][row_off];
                ulonglong2 a01 = pa[0], a23 = pa[1];
                unsigned long long ap[4] = {a01.x, a01.y, a23.x, a23.y};
                const float4* pb = (const float4*)&Bs[cur][kk][col_off];
                float4 b0 = pb[0], b1 = pb[1];
                unsigned long long bj[8];
                bj[0] = pack2(b0.x, b0.x); bj[1] = pack2(b0.y, b0.y);
                bj[2] = pack2(b0.z, b0.z); bj[3] = pack2(b0.w, b0.w);
                bj[4] = pack2(b1.x, b1.x); bj[5] = pack2(b1.y, b1.y);
                bj[6] = pack2(b1.z, b1.z); bj[7] = pack2(b1.w, b1.w);
#pragma unroll
                for (int p = 0; p < 4; ++p)
#pragma unroll
                    for (int j = 0; j < 8; ++j)
                        acc2[p][j] = fma2(ap[p], bj[j], acc2[p][j]);
            }
            if (has_next) {
                int nxt = cur ^ 1;
                As[nxt][lp + 0][lr] = na.x; As[nxt][lp + 1][lr] = na.y;
                As[nxt][lp + 2][lr] = na.z; As[nxt][lp + 3][lr] = na.w;
                Bs[nxt][lp + 0][lr] = nb.x; Bs[nxt][lp + 1][lr] = nb.y;
                Bs[nxt][lp + 2][lr] = nb.z; Bs[nxt][lp + 3][lr] = nb.w;
            }
            __syncthreads();
            cur ^= 1;
        }
#pragma unroll
        for (int p = 0; p < 4; ++p)
#pragma unroll
            for (int j = 0; j < 8; ++j)
                unpack2(acc2[p][j], acc[2 * p][j], acc[2 * p + 1][j]);
    } else {
#pragma unroll
        for (int i = 0; i < 8; ++i)
#pragma unroll
            for (int j = 0; j < 8; ++j) acc[i][j] = 0.f;
        for (int k0 = 0; k0 < K; k0 += TBK) {
            for (int i = tid; i < TBM * TBK; i += 256) {
                int mm = i % TBM, kk = i / TBM;
                int gk = k0 + kk;
                As[0][kk][mm] = (gk < K) ? A[(long long)(m0 + mm) * lda + gk] : 0.f;
            }
            for (int i = tid; i < TBN * TBK; i += 256) {
                int nn = i % TBN, kk = i / TBN;
                int gk = k0 + kk;
                Bs[0][kk][nn] = (gk < K) ? A[(long long)(n0 + nn) * lda + gk] : 0.f;
            }
            __syncthreads();
#pragma unroll
            for (int kk = 0; kk < TBK; ++kk) {
                float ra[8], rb[8];
                const float4* pa = (const float4*)&As[0][kk][row_off];
                const float4* pb = (const float4*)&Bs[0][kk][col_off];
                float4 a0 = pa[0], a1 = pa[1];
                float4 b0 = pb[0], b1 = pb[1];
                ra[0] = a0.x; ra[1] = a0.y; ra[2] = a0.z; ra[3] = a0.w;
                ra[4] = a1.x; ra[5] = a1.y; ra[6] = a1.z; ra[7] = a1.w;
                rb[0] = b0.x; rb[1] = b0.y; rb[2] = b0.z; rb[3] = b0.w;
                rb[4] = b1.x; rb[5] = b1.y; rb[6] = b1.z; rb[7] = b1.w;
#pragma unroll
                for (int i = 0; i < 8; ++i)
#pragma unroll
                    for (int j = 0; j < 8; ++j) acc[i][j] += ra[i] * rb[j];
            }
            __syncthreads();
        }
    }

    float sm[8], sn[8], trr[8], trc[8];
#pragma unroll
    for (int i = 0; i < 8; ++i) {
        sm[i] = sqp[m0 + row_off + i];
        trr[i] = thrp[m0 + row_off + i];
    }
#pragma unroll
    for (int j = 0; j < 8; ++j) {
        sn[j] = sqp[n0 + col_off + j];
        trc[j] = thrp[n0 + col_off + j];
    }
#pragma unroll
    for (int i = 0; i < 8; ++i)
#pragma unroll
        for (int j = 0; j < 8; ++j)
            acc[i][j] = dist_val(sm[i], sn[j], acc[i][j]);

    // ---- row push: 8-lane groups (ly fixed), leader lane = ly*8 ----
    {
        const unsigned grp = 0xFFu << (ly * 8);
        const unsigned below = ((1u << lx) - 1u) << (ly * 8);
        const int leader_lane = ly * 8;
#pragma unroll
        for (int i = 0; i < 8; ++i) {
            const int gm = m0 + row_off + i;
            unsigned pb[8];
            int rank[8];
            int cum = 0;
#pragma unroll
            for (int j = 0; j < 8; ++j) {
                unsigned ball = __ballot_sync(0xFFFFFFFFu, acc[i][j] <= trr[i]) & grp;
                rank[j] = cum + __popc(ball & below);
                cum += __popc(ball);
                pb[j] = ball;
            }
            int base = 0;
            if (lx == 0 && cum > 0) base = atomicAdd(&cntp[gm * CNT_STRIDE], cum);
            base = __shfl_sync(0xFFFFFFFFu, base, leader_lane);
            if (cum > 0) {
                unsigned long long* dst = candp + (size_t)gm * CAND_CAP;
#pragma unroll
                for (int j = 0; j < 8; ++j) {
                    if (pb[j] & (1u << lane)) {
                        int pos = base + rank[j];
                        if (pos < CAND_CAP) {
                            int gn = n0 + col_off + j;
                            dst[pos] = ((unsigned long long)float_key(acc[i][j]) << 32)
                                       | (unsigned int)gn;
                        }
                    }
                }
            }
        }
    }

    // ---- col push (off-diagonal only): 4-lane strided groups (lx fixed) ----
    if (offdiag) {
        const unsigned grp = 0x01010101u << lx;
        const unsigned below = grp & ((1u << lane) - 1u);
        const int leader_lane = lx;
#pragma unroll
        for (int j = 0; j < 8; ++j) {
            const int gn = n0 + col_off + j;
            unsigned pb[8];
            int rank[8];
            int cum = 0;
#pragma unroll
            for (int i = 0; i < 8; ++i) {
                unsigned ball = __ballot_sync(0xFFFFFFFFu, acc[i][j] <= trc[j]) & grp;
                rank[i] = cum + __popc(ball & below);
                cum += __popc(ball);
                pb[i] = ball;
            }
            int base = 0;
            if (ly == 0 && cum > 0) base = atomicAdd(&cntp[gn * CNT_STRIDE], cum);
            base = __shfl_sync(0xFFFFFFFFu, base, leader_lane);
            if (cum > 0) {
                unsigned long long* dst = candp + (size_t)gn * CAND_CAP;
#pragma unroll
                for (int i = 0; i < 8; ++i) {
                    if (pb[i] & (1u << lane)) {
                        int pos = base + rank[i];
                        if (pos < CAND_CAP) {
                            int gm = m0 + row_off + i;
                            dst[pos] = ((unsigned long long)float_key(acc[i][j]) << 32)
                                       | (unsigned int)gm;
                        }
                    }
                }
            }
        }
    }
}

// ----------------------------- thresholds -----------------------------------
// Layer 1: 20th smallest of the 256-subset distances.
__global__ __launch_bounds__(256)
void thr_kernel(const float* __restrict__ sd, float* __restrict__ thr,
                int* __restrict__ cnt) {
    int warp = (blockIdx.x * blockDim.x + threadIdx.x) >> 5;
    int lane = threadIdx.x & 31;
    if (warp >= NROWS) return;
    const float4* row4 = (const float4*)(sd + (size_t)warp * NSUB);

    float loc[KNN];
#pragma unroll
    for (int t = 0; t < KNN; ++t) loc[t] = FLT_MAX;

#pragma unroll
    for (int g = 0; g < 2; ++g) {
        float4 v4 = row4[g * 32 + lane];
        float vals[4] = {v4.x, v4.y, v4.z, v4.w};
#pragma unroll
        for (int s = 0; s < 4; ++s) {
            float v = vals[s];
#pragma unroll
            for (int t = 0; t < KNN; ++t) {
                float mn = fminf(loc[t], v);
                v = fmaxf(loc[t], v);
                loc[t] = mn;
            }
        }
    }

    float thr_f = 0.f;
#pragma unroll
    for (int s = 0; s < KNN; ++s) {
        float v = loc[0];
#pragma unroll
        for (int off = 16; off > 0; off >>= 1)
            v = fminf(v, __shfl_xor_sync(0xFFFFFFFFu, v, off));
        unsigned m = __ballot_sync(0xFFFFFFFFu, loc[0] == v);
        int wlane = __ffs(m) - 1;
        if (lane == wlane) {
#pragma unroll
            for (int t = 0; t < KNN - 1; ++t) loc[t] = loc[t + 1];
            loc[KNN - 1] = FLT_MAX;
        }
        thr_f = v;
    }
    if (lane == 0) {
        thr[warp] = thr_f;
        cnt[warp * CNT_STRIDE] = 0;
    }
}

// Layers 2-4: thr = max distance to the previous layer's 20 neighbors.
// Serial-fma dot (ascending k) + dist_val => bitwise equal to the filter's
// value for the same pair, so the bound is exact. Warp per row.
__global__ __launch_bounds__(256)
void thr_prev_kernel(const float* __restrict__ X, int lda, int D,
                     const float* __restrict__ sq,
                     const int* __restrict__ pidx,
                     float* __restrict__ thr, int* __restrict__ cnt) {
    __shared__ float selfrow[8][128];
    const int warp = threadIdx.x >> 5;
    const int lane = threadIdx.x & 31;
    const int row = blockIdx.x * 8 + warp;
    const int b = row / NPTS;
    const float* xr = X + (size_t)row * lda;
    for (int d = lane; d < D; d += 32) selfrow[warp][d] = xr[d];
    __syncwarp();
    float dist = -FLT_MAX;
    if (lane < KNN) {
        int nb = pidx[(size_t)row * KNN + lane];
        const float* xn = X + ((size_t)b * NPTS + nb) * lda;
        float acc = 0.f;
        for (int d = 0; d < D; ++d)
            acc = __fmaf_rn(selfrow[warp][d], xn[d], acc);
        dist = dist_val(sq[row], sq[(size_t)b * NPTS + nb], acc);
    }
#pragma unroll
    for (int off = 16; off > 0; off >>= 1)
        dist = fmaxf(dist, __shfl_xor_sync(0xFFFFFFFFu, dist, off));
    if (lane == 0) {
        thr[row] = dist;
        cnt[row * CNT_STRIDE] = 0;
    }
}

// -------------- fused: top-20 select + gather + bn/lrelu + sqnorm ------------
// Also writes the 20 indices to idx_out (threshold source for the next layer).
__global__ __launch_bounds__(256)
void topk_gather_kernel(const unsigned long long* __restrict__ cand,
                        const int* __restrict__ cnt,
                        const float* __restrict__ PQ,
                        const float* __restrict__ gamma,
                        const float* __restrict__ beta,
                        float* __restrict__ out, int outLd, int C,
                        float* __restrict__ sqout,
                        int* __restrict__ idx_out) {
    __shared__ int sidx[8][KNN];
    const int warp = threadIdx.x >> 5;
    const int lane = threadIdx.x & 31;
    const int point = blockIdx.x * 8 + warp;
    const int b = point / NPTS;

    // ---- phase 1: top-20 selection ----
    {
        int c = cnt[point * CNT_STRIDE];
        if (c > CAND_CAP) c = CAND_CAP;
        const unsigned long long* buf = cand + (size_t)point * CAND_CAP;
        const unsigned long long SENT = 0xFFFFFFFFFFFFFFFFULL;
        unsigned long long loc[KNN];
#pragma unroll
        for (int t = 0; t < KNN; ++t) loc[t] = SENT;
        for (int i = lane; i < c; i += 32) chain_insert20(loc, buf[i]);

#pragma unroll
        for (int s = 0; s < KNN; ++s) {
            unsigned long long v = loc[0];
            int wl = lane;
#pragma unroll
            for (int off = 16; off > 0; off >>= 1) {
                unsigned long long ov = __shfl_down_sync(0xFFFFFFFFu, v, off);
                int owl = __shfl_down_sync(0xFFFFFFFFu, wl, off);
                if (ov < v) { v = ov; wl = owl; }
            }
            unsigned long long win = __shfl_sync(0xFFFFFFFFu, v, 0);
            int wlane = __shfl_sync(0xFFFFFFFFu, wl, 0);
            if (lane == 0) sidx[warp][s] = (int)(win & 0xFFFFFFFFu);
            if (lane == wlane) {
#pragma unroll
                for (int t = 0; t < KNN - 1; ++t) loc[t] = loc[t + 1];
                loc[KNN - 1] = SENT;
            }
        }
        __syncwarp();
        if (lane < KNN) idx_out[(size_t)point * KNN + lane] = sidx[warp][lane];
    }

    // ---- phase 2: gather + epilogue + sqnorm ----
    const int ld = 2 * C;
    const float4* qrow = (const float4*)(PQ + (size_t)point * ld + C);
    float4* orow = (float4*)(out + (size_t)point * outLd);
    const size_t rowbase = (size_t)b * NPTS;
    const float rs = rsqrtf(1.0f + EPS_BN);
    float ss = 0.f;

    if (C == 64) {
        // pairwise split: c4 = lane&15, neighbors [half*10, half*10+10)
        const int c4 = lane & 15;
        const int half = lane >> 4;
        float4 m = make_float4(-FLT_MAX, -FLT_MAX, -FLT_MAX, -FLT_MAX);
        const int j0 = half * 10;
#pragma unroll
        for (int jj = 0; jj < 10; ++jj) {
            const float4* prow = (const float4*)(PQ + (rowbase + sidx[warp][j0 + jj]) * ld);
            float4 pv = prow[c4];
            m.x = fmaxf(m.x, pv.x); m.y = fmaxf(m.y, pv.y);
            m.z = fmaxf(m.z, pv.z); m.w = fmaxf(m.w, pv.w);
        }
        m.x = fmaxf(m.x, __shfl_xor_sync(0xFFFFFFFFu, m.x, 16));
        m.y = fmaxf(m.y, __shfl_xor_sync(0xFFFFFFFFu, m.y, 16));
        m.z = fmaxf(m.z, __shfl_xor_sync(0xFFFFFFFFu, m.z, 16));
        m.w = fmaxf(m.w, __shfl_xor_sync(0xFFFFFFFFu, m.w, 16));
        if (half == 0) {
            float4 q = qrow[c4];
            float4 gg = ((const float4*)gamma)[c4];
            float4 bb = ((const float4*)beta)[c4];
            float4 v;
            v.x = (m.x + q.x) * (gg.x * rs) + bb.x;
            v.y = (m.y + q.y) * (gg.y * rs) + bb.y;
            v.z = (m.z + q.z) * (gg.z * rs) + bb.z;
            v.w = (m.w + q.w) * (gg.w * rs) + bb.w;
            v.x = (v.x >= 0.f) ? v.x : SLOPE * v.x;
            v.y = (v.y >= 0.f) ? v.y : SLOPE * v.y;
            v.z = (v.z >= 0.f) ? v.z : SLOPE * v.z;
            v.w = (v.w >= 0.f) ? v.w : SLOPE * v.w;
            orow[c4] = v;
            ss = v.x * v.x + v.y * v.y + v.z * v.z + v.w * v.w;
        }
    } else {
        for (int c4 = lane; c4 < C / 4; c4 += 32) {
            float4 m = make_float4(-FLT_MAX, -FLT_MAX, -FLT_MAX, -FLT_MAX);
#pragma unroll 4
            for (int j = 0; j < KNN; ++j) {
                const float4* prow = (const float4*)(PQ + (rowbase + sidx[warp][j]) * ld);
                float4 pv = prow[c4];
                m.x = fmaxf(m.x, pv.x); m.y = fmaxf(m.y, pv.y);
                m.z = fmaxf(m.z, pv.z); m.w = fmaxf(m.w, pv.w);
            }
            float4 q = qrow[c4];
            float4 gg = ((const float4*)gamma)[c4];
            float4 bb = ((const float4*)beta)[c4];
            float4 v;
            v.x = (m.x + q.x) * (gg.x * rs) + bb.x;
            v.y = (m.y + q.y) * (gg.y * rs) + bb.y;
            v.z = (m.z + q.z) * (gg.z * rs) + bb.z;
            v.w = (m.w + q.w) * (gg.w * rs) + bb.w;
            v.x = (v.x >= 0.f) ? v.x : SLOPE * v.x;
            v.y = (v.y >= 0.f) ? v.y : SLOPE * v.y;
            v.z = (v.z >= 0.f) ? v.z : SLOPE * v.z;
            v.w = (v.w >= 0.f) ? v.w : SLOPE * v.w;
            orow[c4] = v;
            ss += v.x * v.x + v.y * v.y + v.z * v.z + v.w * v.w;
        }
    }
#pragma unroll
    for (int off = 16; off > 0; off >>= 1)
        ss += __shfl_down_sync(0xFFFFFFFFu, ss, off);
    if (lane == 0) sqout[point] = ss;
}

// ----------------------------- final pool merge -------------------------------
#define PCHUNK 32

__global__ void reduce2_kernel(const float* __restrict__ pmax,
                               const float* __restrict__ psum,
                               float* __restrict__ out) {
    int b = blockIdx.x;
    int c = threadIdx.x;
    float mx = -FLT_MAX, sm = 0.f;
#pragma unroll
    for (int q = 0; q < PCHUNK; ++q) {
        mx = fmaxf(mx, pmax[(b * PCHUNK + q) * 512 + c]);
        sm += psum[(b * PCHUNK + q) * 512 + c];
    }
    out[b * 1024 + c]       = mx;
    out[b * 1024 + 512 + c] = sm * (1.0f / NPTS);
}

// ----------------------------- host driver ----------------------------------

static void run_edge_conv(const float* X, int lda, int D, int C,
                          const float* g, const float* b,
                          float* h_out_col, bool first_layer,
                          float* p_sq, float* p_sub, float* p_thr, int* p_cnt,
                          unsigned long long* p_cand, int* p_idx,
                          float* p_PQ, const float* p_wc) {
    if (first_layer) {
        // subset dist: every point vs first NSUB points of its batch
        dim3 gs(NSUB / TBN, NPTS / TBM, BATCH);
        gemm_nt_kernel<1><<<gs, 256>>>(X, lda, (long long)NPTS * lda,
                                       X, lda, (long long)NPTS * lda,
                                       p_sub, NSUB, (long long)NPTS * NSUB,
                                       NPTS, NSUB, D,
                                       p_sq, NPTS, nullptr, nullptr,
                                       nullptr, nullptr);
        thr_kernel<<<NROWS / 8, 256>>>(p_sub, p_thr, p_cnt);
    } else {
        thr_prev_kernel<<<NROWS / 8, 256>>>(X, lda, D, p_sq, p_idx, p_thr, p_cnt);
    }

    // symmetric triangular filter (no dist store)
    dim3 gd(NPAIRS, 1, BATCH);
    dist_filter_kernel<<<gd, 256>>>(X, lda, D, p_sq, p_thr, p_cnt, p_cand);

    dim3 gp((2 * C) / TBN, NROWS / TBM, 1);
    gemm_nt_kernel<0><<<gp, 256>>>(X, lda, 0, p_wc, D, 0,
                                   p_PQ, 2 * C, 0, NROWS, 2 * C, D,
                                   nullptr, 0, nullptr, nullptr,
                                   nullptr, nullptr);

    // fused top-20 + gather + bn/lrelu + sqnorm (+ idx for next layer's thr)
    topk_gather_kernel<<<NROWS / 8, 256>>>(p_cand, p_cnt, p_PQ, g, b,
                                           h_out_col, 512, C, p_sq, p_idx);
}

extern "C" void kernel_launch(void* const* d_in, const int* in_sizes, int n_in,
                              void* d_out, int out_size) {
    const float* x = (const float*)d_in[0];
    int wb = 1;
    if (n_in > 1 && in_sizes[1] == 1) wb = 2;

    const float* W1 = (const float*)d_in[wb + 0];
    const float* g1 = (const float*)d_in[wb + 1];
    const float* b1 = (const float*)d_in[wb + 2];
    const float* W2 = (const float*)d_in[wb + 3];
    const float* g2 = (const float*)d_in[wb + 4];
    const float* b2 = (const float*)d_in[wb + 5];
    const float* W3 = (const float*)d_in[wb + 6];
    const float* g3 = (const float*)d_in[wb + 7];
    const float* b3 = (const float*)d_in[wb + 8];
    const float* W4 = (const float*)d_in[wb + 9];
    const float* g4 = (const float*)d_in[wb + 10];
    const float* b4 = (const float*)d_in[wb + 11];
    const float* W5 = (const float*)d_in[wb + 12];
    const float* g5 = (const float*)d_in[wb + 13];
    const float* b5 = (const float*)d_in[wb + 14];

    void *p;
    cudaGetSymbolAddress(&p, g_x0);    float* x0   = (float*)p;
    cudaGetSymbolAddress(&p, g_h);     float* h    = (float*)p;
    cudaGetSymbolAddress(&p, g_sq);    float* sq   = (float*)p;
    cudaGetSymbolAddress(&p, g_idx);   int*   idx  = (int*)p;
    cudaGetSymbolAddress(&p, g_PQ);    float* PQ   = (float*)p;
    cudaGetSymbolAddress(&p, g_wcomb); float* wc   = (float*)p;
    cudaGetSymbolAddress(&p, g_sub);   float* sub  = (float*)p;
    cudaGetSymbolAddress(&p, g_thr);   float* thr  = (float*)p;
    cudaGetSymbolAddress(&p, g_cnt);   int*   cnt  = (int*)p;
    cudaGetSymbolAddress(&p, g_cand);  unsigned long long* cand = (unsigned long long*)p;
    cudaGetSymbolAddress(&p, g_pmax);  float* pmax = (float*)p;
    cudaGetSymbolAddress(&p, g_psum);  float* psum = (float*)p;

    transpose_sq_kernel<<<(NROWS + 255) / 256, 256>>>(x, x0, sq);
    {
        int total = 2 * (64 * 3 + 64 * 64 + 128 * 64 + 256 * 128);
        wcomb_all_kernel<<<(total + 255) / 256, 256>>>(W1, W2, W3, W4, wc);
    }

    run_edge_conv(x0,      3,   3,   64,  g1, b1, h + 0,   true,  sq, sub, thr, cnt, cand, idx, PQ, wc + WCO1);
    run_edge_conv(h + 0,   512, 64,  64,  g2, b2, h + 64,  false, sq, sub, thr, cnt, cand, idx, PQ, wc + WCO2);
    run_edge_conv(h + 64,  512, 64,  128, g3, b3, h + 128, false, sq, sub, thr, cnt, cand, idx, PQ, wc + WCO3);
    run_edge_conv(h + 128, 512, 128, 256, g4, b4, h + 256, false, sq, sub, thr, cnt, cand, idx, PQ, wc + WCO4);

    // final 1x1 conv (512->512): bn+lrelu + pooling partials fused, no y store
    dim3 gf(512 / TBN, NROWS / TBM, 1);
    gemm_nt_kernel<2><<<gf, 256>>>(h, 512, 0, W5, 512, 0,
                                   nullptr, 0, 0, NROWS, 512, 512,
                                   nullptr, 0, g5, b5,
                                   pmax, psum);

    reduce2_kernel<<<BATCH, 512>>>(pmax, psum, (float*)d_out);
}